// round 1
// baseline (speedup 1.0000x reference)
#include <cuda_runtime.h>
#include <cuda_bf16.h>
#include <math.h>

#define NN 200000
#define EE 400000
#define GG 8000
#define HH 256
#define H4 1024
#define LL 5
#define NP 25   // nodes per graph = NN/GG

// ---------------- scratch (device globals; no allocations allowed) ----------
__device__ float g_h   [(size_t)NN * HH];
__device__ float g_hin [(size_t)NN * HH];
__device__ float g_aggr[(size_t)NN * HH];   // reused as GEMM2 raw output
__device__ float g_hid [(size_t)NN * H4];
__device__ float g_vn  [(size_t)GG * HH];
__device__ float g_vp  [(size_t)GG * HH];   // segment_max result; reused for segment_sum
__device__ float g_gh  [(size_t)GG * H4];
__device__ float g_t   [(size_t)GG * HH];

// ---------------- helpers ----------------------------------------------------
__device__ __forceinline__ float gelu_f(float x) {
    return 0.5f * x * (1.0f + erff(x * 0.70710678118654752f));
}

__device__ __forceinline__ void block_reduce2(float& s, float& ss) {
    // 256-thread block reduction of two values, broadcast result to all threads
    __shared__ float r1[8], r2[8], fin[2];
    #pragma unroll
    for (int o = 16; o > 0; o >>= 1) {
        s  += __shfl_down_sync(0xffffffffu, s,  o);
        ss += __shfl_down_sync(0xffffffffu, ss, o);
    }
    int w = threadIdx.x >> 5, l = threadIdx.x & 31;
    if (l == 0) { r1[w] = s; r2[w] = ss; }
    __syncthreads();
    if (threadIdx.x < 32) {
        float a = (threadIdx.x < 8) ? r1[threadIdx.x] : 0.f;
        float b = (threadIdx.x < 8) ? r2[threadIdx.x] : 0.f;
        #pragma unroll
        for (int o = 4; o > 0; o >>= 1) {
            a += __shfl_down_sync(0xffffffffu, a, o);
            b += __shfl_down_sync(0xffffffffu, b, o);
        }
        if (threadIdx.x == 0) { fin[0] = a; fin[1] = b; }
    }
    __syncthreads();
    s = fin[0]; ss = fin[1];
}

// ---------------- kernels -----------------------------------------------------

// h[i,:] = atom_emb[x[i],:]
__global__ void init_h_kernel(const int* __restrict__ x,
                              const float* __restrict__ emb,
                              float* __restrict__ h) {
    size_t idx = (size_t)blockIdx.x * 256 + threadIdx.x;   // NN*64 items
    int i = (int)(idx >> 6);
    int c = (int)(idx & 63) << 2;
    int a = x[i];
    *(float4*)(h + (size_t)i * HH + c) = *(const float4*)(emb + (size_t)a * HH + c);
}

// vn[g,:] = vn_emb[0,:]
__global__ void init_vn_kernel(const float* __restrict__ vn_emb,
                               float* __restrict__ vn) {
    int idx = blockIdx.x * 256 + threadIdx.x;              // GG*HH items
    vn[idx] = vn_emb[idx & (HH - 1)];
}

// h += vn[batch]; h_in = h; aggr = 0
__global__ void addvn_kernel(const float* __restrict__ vn,
                             const int* __restrict__ batch,
                             float* __restrict__ h,
                             float* __restrict__ hin,
                             float* __restrict__ aggr) {
    size_t idx = (size_t)blockIdx.x * 256 + threadIdx.x;   // NN*64 items
    int i = (int)(idx >> 6);
    int c = (int)(idx & 63) << 2;
    int g = batch[i];
    float4 hv = *(float4*)(h + (size_t)i * HH + c);
    float4 vv = *(const float4*)(vn + (size_t)g * HH + c);
    hv.x += vv.x; hv.y += vv.y; hv.z += vv.z; hv.w += vv.w;
    *(float4*)(h   + (size_t)i * HH + c) = hv;
    *(float4*)(hin + (size_t)i * HH + c) = hv;
    *(float4*)(aggr + (size_t)i * HH + c) = make_float4(0.f, 0.f, 0.f, 0.f);
}

// per edge: aggr[dst] += gelu(h[src] + bond[attr])
__global__ void edge_kernel(const int* __restrict__ src,
                            const int* __restrict__ dst,
                            const int* __restrict__ attr,
                            const float* __restrict__ bond,
                            const float* __restrict__ h,
                            float* __restrict__ aggr) {
    size_t idx = (size_t)blockIdx.x * 256 + threadIdx.x;   // EE*64 items
    int e = (int)(idx >> 6);
    int c = (int)(idx & 63) << 2;
    int s = __ldg(src + e), d = __ldg(dst + e), a = __ldg(attr + e);
    float4 hv = *(const float4*)(h + (size_t)s * HH + c);
    float4 bv = *(const float4*)(bond + (size_t)a * HH + c);
    float4 m;
    m.x = gelu_f(hv.x + bv.x);
    m.y = gelu_f(hv.y + bv.y);
    m.z = gelu_f(hv.z + bv.z);
    m.w = gelu_f(hv.w + bv.w);
    float* p = aggr + (size_t)d * HH + c;
    atomicAdd(p + 0, m.x);
    atomicAdd(p + 1, m.y);
    atomicAdd(p + 2, m.z);
    atomicAdd(p + 3, m.w);
}

// C[M,Nn] = A_eff[M,K] @ B[K,Nn] + bias;  A_eff = (1+eps)*A + A2 when A2 != null
// 128x128 block tile, BK=16, 256 threads, 8x8 per-thread accumulators.
__global__ void __launch_bounds__(256)
gemm_kernel(const float* __restrict__ A, const float* __restrict__ A2,
            const float* __restrict__ eps_ptr, int eps_idx,
            const float* __restrict__ B, const float* __restrict__ bias,
            float* __restrict__ C, int M, int Nn, int K) {
    __shared__ float As[16][128];   // transposed: As[k][m]
    __shared__ float Bs[16][128];
    int tid = threadIdx.x;
    int tx = tid & 15;
    int ty = tid >> 4;
    int row0 = blockIdx.y * 128;
    int col0 = blockIdx.x * 128;
    float alpha = 1.0f;
    if (A2) alpha = 1.0f + __ldg(&eps_ptr[eps_idx]);

    float acc[8][8];
    #pragma unroll
    for (int i = 0; i < 8; i++)
        #pragma unroll
        for (int j = 0; j < 8; j++) acc[i][j] = 0.f;

    for (int kt = 0; kt < K; kt += 16) {
        #pragma unroll
        for (int i = 0; i < 2; i++) {
            int idx = tid + i * 256;            // 0..511
            int r   = idx >> 2;                 // 0..127
            int k4  = (idx & 3) << 2;           // 0,4,8,12
            int gr  = row0 + r;
            float4 v = make_float4(0.f, 0.f, 0.f, 0.f);
            if (gr < M) {
                v = *(const float4*)(A + (size_t)gr * K + kt + k4);
                if (A2) {
                    float4 w = *(const float4*)(A2 + (size_t)gr * K + kt + k4);
                    v.x = alpha * v.x + w.x;
                    v.y = alpha * v.y + w.y;
                    v.z = alpha * v.z + w.z;
                    v.w = alpha * v.w + w.w;
                }
            }
            As[k4 + 0][r] = v.x; As[k4 + 1][r] = v.y;
            As[k4 + 2][r] = v.z; As[k4 + 3][r] = v.w;
        }
        #pragma unroll
        for (int i = 0; i < 2; i++) {
            int idx = tid + i * 256;
            int k   = idx >> 5;                 // 0..15
            int c4  = (idx & 31) << 2;          // 0..124
            float4 v = *(const float4*)(B + (size_t)(kt + k) * Nn + col0 + c4);
            *(float4*)&Bs[k][c4] = v;
        }
        __syncthreads();
        #pragma unroll
        for (int k = 0; k < 16; k++) {
            float af[8], bf[8];
            #pragma unroll
            for (int i = 0; i < 8; i++) af[i] = As[k][ty * 8 + i];
            #pragma unroll
            for (int j = 0; j < 8; j++) bf[j] = Bs[k][tx * 8 + j];
            #pragma unroll
            for (int i = 0; i < 8; i++)
                #pragma unroll
                for (int j = 0; j < 8; j++)
                    acc[i][j] += af[i] * bf[j];
        }
        __syncthreads();
    }
    #pragma unroll
    for (int i = 0; i < 8; i++) {
        int gr = row0 + ty * 8 + i;
        if (gr >= M) continue;
        #pragma unroll
        for (int j = 0; j < 8; j++) {
            int gc = col0 + tx * 8 + j;
            C[(size_t)gr * Nn + gc] = acc[i][j] + __ldg(&bias[gc]);
        }
    }
}

// row-wise LayerNorm (+ optional exact gelu). One block (256 thr) per row. In-place safe.
__global__ void ln_act_kernel(const float* __restrict__ in,
                              const float* __restrict__ gw,
                              const float* __restrict__ bw,
                              float* __restrict__ out, int W, int do_gelu) {
    size_t row = blockIdx.x;
    const float* x = in + row * W;
    float* y = out + row * W;
    float s = 0.f, ss = 0.f;
    for (int j = threadIdx.x; j < W; j += 256) {
        float v = x[j]; s += v; ss += v * v;
    }
    block_reduce2(s, ss);
    float m = s / (float)W;
    float rstd = rsqrtf(ss / (float)W - m * m + 1e-5f);
    for (int j = threadIdx.x; j < W; j += 256) {
        float v = (x[j] - m) * rstd * gw[j] + bw[j];
        if (do_gelu) v = gelu_f(v);
        y[j] = v;
    }
}

// h = gelu?(LN(t2; g,b)) + h_in     (W = 256, 1 elem/thread)
__global__ void ln_res_kernel(const float* __restrict__ t2,
                              const float* __restrict__ gw,
                              const float* __restrict__ bw,
                              const float* __restrict__ hin,
                              float* __restrict__ hout, int do_gelu) {
    size_t row = blockIdx.x;
    int j = threadIdx.x;
    float v = t2[row * HH + j];
    float s = v, ss = v * v;
    block_reduce2(s, ss);
    float m = s * (1.f / HH);
    float rstd = rsqrtf(ss * (1.f / HH) - m * m + 1e-5f);
    float o = (v - m) * rstd * gw[j] + bw[j];
    if (do_gelu) o = gelu_f(o);
    hout[row * HH + j] = o + hin[row * HH + j];
}

// vp[g,j] = max over 25 contiguous nodes (batch is sorted, NP nodes per graph)
__global__ void segmax_kernel(const float* __restrict__ hin, float* __restrict__ vp) {
    int idx = blockIdx.x * 256 + threadIdx.x;              // GG*HH items
    int g = idx >> 8;
    int j = idx & (HH - 1);
    const float* base = hin + (size_t)g * NP * HH + j;
    float m = base[0];
    #pragma unroll
    for (int t = 1; t < NP; t++) m = fmaxf(m, base[(size_t)t * HH]);
    vp[idx] = m;
}

__global__ void segsum_kernel(const float* __restrict__ h, float* __restrict__ o) {
    int idx = blockIdx.x * 256 + threadIdx.x;              // GG*HH items
    int g = idx >> 8;
    int j = idx & (HH - 1);
    const float* base = h + (size_t)g * NP * HH + j;
    float s = 0.f;
    #pragma unroll
    for (int t = 0; t < NP; t++) s += base[(size_t)t * HH];
    o[idx] = s;
}

__global__ void vnadd_kernel(float* __restrict__ vn, const float* __restrict__ t) {
    int idx = blockIdx.x * 256 + threadIdx.x;
    vn[idx] += t[idx];
}

// z[row,:] /= ||z[row,:]||   (in place on d_out)
__global__ void l2norm_kernel(float* __restrict__ z) {
    size_t row = blockIdx.x;
    int j = threadIdx.x;
    float v = z[row * HH + j];
    float s = v * v, dummy = 0.f;
    block_reduce2(s, dummy);
    z[row * HH + j] = v * rsqrtf(s);
}

// ---------------- host orchestration -----------------------------------------
extern "C" void kernel_launch(void* const* d_in, const int* in_sizes, int n_in,
                              void* d_out, int out_size) {
    const int*   x        = (const int*)  d_in[0];
    const int*   eidx     = (const int*)  d_in[1];
    const int*   eattr    = (const int*)  d_in[2];
    const int*   batch    = (const int*)  d_in[3];
    const float* atom_emb = (const float*)d_in[4];
    const float* vn_emb   = (const float*)d_in[5];
    const float* bond_emb = (const float*)d_in[6];
    const float* epsv     = (const float*)d_in[7];
    const float* c_w1  = (const float*)d_in[8];
    const float* c_b1  = (const float*)d_in[9];
    const float* c_lng = (const float*)d_in[10];
    const float* c_lnb = (const float*)d_in[11];
    const float* c_w2  = (const float*)d_in[12];
    const float* c_b2  = (const float*)d_in[13];
    const float* n_g   = (const float*)d_in[14];
    const float* n_b   = (const float*)d_in[15];
    const float* v_w1  = (const float*)d_in[16];
    const float* v_b1  = (const float*)d_in[17];
    const float* v_lng = (const float*)d_in[18];
    const float* v_lnb = (const float*)d_in[19];
    const float* v_w2  = (const float*)d_in[20];
    const float* v_b2  = (const float*)d_in[21];
    const float* p_w1  = (const float*)d_in[22];
    const float* p_b1  = (const float*)d_in[23];
    const float* p_lng = (const float*)d_in[24];
    const float* p_lnb = (const float*)d_in[25];
    const float* p_w2  = (const float*)d_in[26];
    const float* p_b2  = (const float*)d_in[27];
    float* out = (float*)d_out;

    float *h, *hin, *aggr, *hid, *vn, *vp, *gh, *t;
    cudaGetSymbolAddress((void**)&h,    g_h);
    cudaGetSymbolAddress((void**)&hin,  g_hin);
    cudaGetSymbolAddress((void**)&aggr, g_aggr);
    cudaGetSymbolAddress((void**)&hid,  g_hid);
    cudaGetSymbolAddress((void**)&vn,   g_vn);
    cudaGetSymbolAddress((void**)&vp,   g_vp);
    cudaGetSymbolAddress((void**)&gh,   g_gh);
    cudaGetSymbolAddress((void**)&t,    g_t);

    const int* src = eidx;
    const int* dst = eidx + EE;

    const int nodeBlocks  = NN * 64 / 256;   // 50000
    const int edgeBlocks  = EE * 64 / 256;   // 100000
    const int gBlocks     = GG * HH / 256;   // 8000
    const dim3 gemmN1(H4 / 128, (NN + 127) / 128);
    const dim3 gemmN2(HH / 128, (NN + 127) / 128);
    const dim3 gemmG1(H4 / 128, (GG + 127) / 128);
    const dim3 gemmG2(HH / 128, (GG + 127) / 128);

    init_h_kernel<<<nodeBlocks, 256>>>(x, atom_emb, h);
    init_vn_kernel<<<gBlocks, 256>>>(vn_emb, vn);

    for (int l = 0; l < LL; l++) {
        addvn_kernel<<<nodeBlocks, 256>>>(vn, batch, h, hin, aggr);
        edge_kernel<<<edgeBlocks, 256>>>(src, dst, eattr,
                                         bond_emb + (size_t)l * 5 * HH, h, aggr);
        // hid = (1+eps)*h + aggr  @ c_w1 + b1
        gemm_kernel<<<gemmN1, 256>>>(h, aggr, epsv, l,
                                     c_w1 + (size_t)l * HH * H4,
                                     c_b1 + (size_t)l * H4, hid, NN, H4, HH);
        ln_act_kernel<<<NN, 256>>>(hid, c_lng + (size_t)l * H4,
                                   c_lnb + (size_t)l * H4, hid, H4, 1);
        // aggr(reused) = hid @ c_w2 + b2
        gemm_kernel<<<gemmN2, 256>>>(hid, nullptr, nullptr, 0,
                                     c_w2 + (size_t)l * H4 * HH,
                                     c_b2 + (size_t)l * HH, aggr, NN, HH, H4);
        ln_res_kernel<<<NN, 256>>>(aggr, n_g + (size_t)l * HH,
                                   n_b + (size_t)l * HH, hin, h,
                                   (l < LL - 1) ? 1 : 0);
        if (l < LL - 1) {
            segmax_kernel<<<gBlocks, 256>>>(hin, vp);
            gemm_kernel<<<gemmG1, 256>>>(vp, nullptr, nullptr, 0,
                                         v_w1 + (size_t)l * HH * H4,
                                         v_b1 + (size_t)l * H4, gh, GG, H4, HH);
            ln_act_kernel<<<GG, 256>>>(gh, v_lng + (size_t)l * H4,
                                       v_lnb + (size_t)l * H4, gh, H4, 1);
            gemm_kernel<<<gemmG2, 256>>>(gh, nullptr, nullptr, 0,
                                         v_w2 + (size_t)l * H4 * HH,
                                         v_b2 + (size_t)l * HH, t, GG, HH, H4);
            vnadd_kernel<<<gBlocks, 256>>>(vn, t);
        }
    }

    segsum_kernel<<<gBlocks, 256>>>(h, vp);                 // vp reused as h_graph
    gemm_kernel<<<gemmG2, 256>>>(vp, nullptr, nullptr, 0, p_w1, p_b1, t, GG, HH, HH);
    ln_act_kernel<<<GG, 256>>>(t, p_lng, p_lnb, t, HH, 1);
    gemm_kernel<<<gemmG2, 256>>>(t, nullptr, nullptr, 0, p_w2, p_b2, out, GG, HH, HH);
    l2norm_kernel<<<GG, 256>>>(out);
}

// round 2
// speedup vs baseline: 2.1301x; 2.1301x over previous
#include <cuda_runtime.h>
#include <cuda_bf16.h>
#include <math.h>

#define NN 200000
#define EE 400000
#define GG 8000
#define HH 256
#define H4 1024
#define LL 5
#define NP 25   // nodes per graph = NN/GG

// ---------------- scratch (device globals; no allocations allowed) ----------
__device__ float g_h   [(size_t)NN * HH];
__device__ float g_hin [(size_t)NN * HH];
__device__ float g_aggr[(size_t)NN * HH];   // reused as GEMM2 raw output
__device__ float g_hid [(size_t)NN * H4];
__device__ float g_vn  [(size_t)GG * HH];
__device__ float g_vp  [(size_t)GG * HH];   // segment_max result; reused for segment_sum
__device__ float g_gh  [(size_t)GG * H4];
__device__ float g_t   [(size_t)GG * HH];

// ---------------- helpers ----------------------------------------------------
__device__ __forceinline__ float gelu_f(float x) {
    return 0.5f * x * (1.0f + erff(x * 0.70710678118654752f));
}

__device__ __forceinline__ unsigned cvt_tf32(float x) {
    unsigned u;
    asm("cvt.rna.tf32.f32 %0, %1;" : "=r"(u) : "f"(x));
    return u;
}

__device__ __forceinline__ void block_reduce2(float& s, float& ss) {
    __shared__ float r1[8], r2[8], fin[2];
    #pragma unroll
    for (int o = 16; o > 0; o >>= 1) {
        s  += __shfl_down_sync(0xffffffffu, s,  o);
        ss += __shfl_down_sync(0xffffffffu, ss, o);
    }
    int w = threadIdx.x >> 5, l = threadIdx.x & 31;
    if (l == 0) { r1[w] = s; r2[w] = ss; }
    __syncthreads();
    if (threadIdx.x < 32) {
        float a = (threadIdx.x < 8) ? r1[threadIdx.x] : 0.f;
        float b = (threadIdx.x < 8) ? r2[threadIdx.x] : 0.f;
        #pragma unroll
        for (int o = 4; o > 0; o >>= 1) {
            a += __shfl_down_sync(0xffffffffu, a, o);
            b += __shfl_down_sync(0xffffffffu, b, o);
        }
        if (threadIdx.x == 0) { fin[0] = a; fin[1] = b; }
    }
    __syncthreads();
    s = fin[0]; ss = fin[1];
}

// ---------------- kernels -----------------------------------------------------

__global__ void init_h_kernel(const int* __restrict__ x,
                              const float* __restrict__ emb,
                              float* __restrict__ h) {
    size_t idx = (size_t)blockIdx.x * 256 + threadIdx.x;   // NN*64 items
    int i = (int)(idx >> 6);
    int c = (int)(idx & 63) << 2;
    int a = x[i];
    *(float4*)(h + (size_t)i * HH + c) = *(const float4*)(emb + (size_t)a * HH + c);
}

__global__ void init_vn_kernel(const float* __restrict__ vn_emb,
                               float* __restrict__ vn) {
    int idx = blockIdx.x * 256 + threadIdx.x;              // GG*HH items
    vn[idx] = vn_emb[idx & (HH - 1)];
}

// h += vn[batch]; h_in = h; aggr = 0
__global__ void addvn_kernel(const float* __restrict__ vn,
                             const int* __restrict__ batch,
                             float* __restrict__ h,
                             float* __restrict__ hin,
                             float* __restrict__ aggr) {
    size_t idx = (size_t)blockIdx.x * 256 + threadIdx.x;   // NN*64 items
    int i = (int)(idx >> 6);
    int c = (int)(idx & 63) << 2;
    int g = batch[i];
    float4 hv = *(float4*)(h + (size_t)i * HH + c);
    float4 vv = *(const float4*)(vn + (size_t)g * HH + c);
    hv.x += vv.x; hv.y += vv.y; hv.z += vv.z; hv.w += vv.w;
    *(float4*)(h   + (size_t)i * HH + c) = hv;
    *(float4*)(hin + (size_t)i * HH + c) = hv;
    *(float4*)(aggr + (size_t)i * HH + c) = make_float4(0.f, 0.f, 0.f, 0.f);
}

// per edge: aggr[dst] += gelu(h[src] + bond[attr])
__global__ void edge_kernel(const int* __restrict__ src,
                            const int* __restrict__ dst,
                            const int* __restrict__ attr,
                            const float* __restrict__ bond,
                            const float* __restrict__ h,
                            float* __restrict__ aggr) {
    size_t idx = (size_t)blockIdx.x * 256 + threadIdx.x;   // EE*64 items
    int e = (int)(idx >> 6);
    int c = (int)(idx & 63) << 2;
    int s = __ldg(src + e), d = __ldg(dst + e), a = __ldg(attr + e);
    float4 hv = *(const float4*)(h + (size_t)s * HH + c);
    float4 bv = *(const float4*)(bond + (size_t)a * HH + c);
    float4 m;
    m.x = gelu_f(hv.x + bv.x);
    m.y = gelu_f(hv.y + bv.y);
    m.z = gelu_f(hv.z + bv.z);
    m.w = gelu_f(hv.w + bv.w);
    float* p = aggr + (size_t)d * HH + c;
    atomicAdd(p + 0, m.x);
    atomicAdd(p + 1, m.y);
    atomicAdd(p + 2, m.z);
    atomicAdd(p + 3, m.w);
}

// ---------------- TF32 tensor-core GEMM ---------------------------------------
// C[M,Nn] = A_eff[M,K] @ B[K,Nn] + bias; A_eff = (1+eps)*A + A2 when A2 != null.
// Block 128x128, BK=32, 4 warps (128 thr), warp tile 64x64, mma.m16n8k8.tf32.
#define GPAD 36   // smem row pitch (words): frag loads conflict-free

__global__ void __launch_bounds__(128)
gemm_tc_kernel(const float* __restrict__ A, const float* __restrict__ A2,
               const float* __restrict__ eps_ptr, int eps_idx,
               const float* __restrict__ B, const float* __restrict__ bias,
               float* __restrict__ C, int M, int Nn, int K) {
    __shared__ unsigned As[128 * GPAD];
    __shared__ unsigned Bs[128 * GPAD];

    const int tid  = threadIdx.x;
    const int lane = tid & 31;
    const int warp = tid >> 5;
    const int wm   = (warp >> 1) * 64;
    const int wn   = (warp & 1) * 64;
    const int qr   = lane >> 2;      // 0..7
    const int qc   = lane & 3;       // 0..3

    const int row0 = blockIdx.y * 128;
    const int col0 = blockIdx.x * 128;

    float alpha = 1.0f;
    if (A2) alpha = 1.0f + __ldg(&eps_ptr[eps_idx]);

    float acc[4][8][4];
    #pragma unroll
    for (int mi = 0; mi < 4; mi++)
        #pragma unroll
        for (int ni = 0; ni < 8; ni++)
            #pragma unroll
            for (int r = 0; r < 4; r++) acc[mi][ni][r] = 0.f;

    for (int kt = 0; kt < K; kt += 32) {
        // ---- load A tile (128x32): 8 float4 per thread, coalesced ----
        #pragma unroll
        for (int it = 0; it < 8; it++) {
            int idx = tid + it * 128;          // 0..1023
            int r   = idx >> 3;                // 0..127
            int c4  = (idx & 7) << 2;          // 0..28
            int gr  = row0 + r;
            float4 v = make_float4(0.f, 0.f, 0.f, 0.f);
            if (gr < M) {
                v = *(const float4*)(A + (size_t)gr * K + kt + c4);
                if (A2) {
                    float4 w = *(const float4*)(A2 + (size_t)gr * K + kt + c4);
                    v.x = fmaf(alpha, v.x, w.x);
                    v.y = fmaf(alpha, v.y, w.y);
                    v.z = fmaf(alpha, v.z, w.z);
                    v.w = fmaf(alpha, v.w, w.w);
                }
            }
            unsigned* p = &As[r * GPAD + c4];
            p[0] = cvt_tf32(v.x); p[1] = cvt_tf32(v.y);
            p[2] = cvt_tf32(v.z); p[3] = cvt_tf32(v.w);
        }
        // ---- load B tile (32x128) transposed to Bs[n][k]: coalesced in n ----
        #pragma unroll
        for (int it = 0; it < 8; it++) {
            int idx = tid + it * 128;          // 0..1023
            int n   = idx & 127;
            int k4  = (idx >> 7) << 2;         // 0,4,...,28
            #pragma unroll
            for (int j = 0; j < 4; j++) {
                float v = B[(size_t)(kt + k4 + j) * Nn + col0 + n];
                Bs[n * GPAD + k4 + j] = cvt_tf32(v);
            }
        }
        __syncthreads();

        #pragma unroll
        for (int ks = 0; ks < 4; ks++) {
            const int ko = ks * 8;
            unsigned af[4][4];
            #pragma unroll
            for (int mi = 0; mi < 4; mi++) {
                const unsigned* r0p = &As[(wm + mi * 16 + qr) * GPAD + ko + qc];
                const unsigned* r1p = r0p + 8 * GPAD;
                af[mi][0] = r0p[0];
                af[mi][1] = r1p[0];
                af[mi][2] = r0p[4];
                af[mi][3] = r1p[4];
            }
            unsigned bf[8][2];
            #pragma unroll
            for (int ni = 0; ni < 8; ni++) {
                const unsigned* bp = &Bs[(wn + ni * 8 + qr) * GPAD + ko + qc];
                bf[ni][0] = bp[0];
                bf[ni][1] = bp[4];
            }
            #pragma unroll
            for (int mi = 0; mi < 4; mi++)
                #pragma unroll
                for (int ni = 0; ni < 8; ni++) {
                    asm volatile(
                        "mma.sync.aligned.m16n8k8.row.col.f32.tf32.tf32.f32 "
                        "{%0,%1,%2,%3}, {%4,%5,%6,%7}, {%8,%9}, {%0,%1,%2,%3};"
                        : "+f"(acc[mi][ni][0]), "+f"(acc[mi][ni][1]),
                          "+f"(acc[mi][ni][2]), "+f"(acc[mi][ni][3])
                        : "r"(af[mi][0]), "r"(af[mi][1]),
                          "r"(af[mi][2]), "r"(af[mi][3]),
                          "r"(bf[ni][0]), "r"(bf[ni][1]));
                }
        }
        __syncthreads();
    }

    // ---- epilogue: acc layout c0:(r,c) c1:(r,c+1) c2:(r+8,c) c3:(r+8,c+1)
    #pragma unroll
    for (int mi = 0; mi < 4; mi++) {
        int r0 = row0 + wm + mi * 16 + qr;
        int r1 = r0 + 8;
        #pragma unroll
        for (int ni = 0; ni < 8; ni++) {
            int cc = col0 + wn + ni * 8 + qc * 2;
            float2 bv = *(const float2*)(bias + cc);
            if (r0 < M) {
                float2 o = make_float2(acc[mi][ni][0] + bv.x, acc[mi][ni][1] + bv.y);
                *(float2*)(C + (size_t)r0 * Nn + cc) = o;
            }
            if (r1 < M) {
                float2 o = make_float2(acc[mi][ni][2] + bv.x, acc[mi][ni][3] + bv.y);
                *(float2*)(C + (size_t)r1 * Nn + cc) = o;
            }
        }
    }
}

// row-wise LayerNorm (+ optional exact gelu). One block (256 thr) per row.
__global__ void ln_act_kernel(const float* __restrict__ in,
                              const float* __restrict__ gw,
                              const float* __restrict__ bw,
                              float* __restrict__ out, int W, int do_gelu) {
    size_t row = blockIdx.x;
    const float* x = in + row * W;
    float* y = out + row * W;
    float s = 0.f, ss = 0.f;
    for (int j = threadIdx.x; j < W; j += 256) {
        float v = x[j]; s += v; ss += v * v;
    }
    block_reduce2(s, ss);
    float m = s / (float)W;
    float rstd = rsqrtf(ss / (float)W - m * m + 1e-5f);
    for (int j = threadIdx.x; j < W; j += 256) {
        float v = (x[j] - m) * rstd * gw[j] + bw[j];
        if (do_gelu) v = gelu_f(v);
        y[j] = v;
    }
}

// h = gelu?(LN(t2; g,b)) + h_in     (W = 256, 1 elem/thread)
__global__ void ln_res_kernel(const float* __restrict__ t2,
                              const float* __restrict__ gw,
                              const float* __restrict__ bw,
                              const float* __restrict__ hin,
                              float* __restrict__ hout, int do_gelu) {
    size_t row = blockIdx.x;
    int j = threadIdx.x;
    float v = t2[row * HH + j];
    float s = v, ss = v * v;
    block_reduce2(s, ss);
    float m = s * (1.f / HH);
    float rstd = rsqrtf(ss * (1.f / HH) - m * m + 1e-5f);
    float o = (v - m) * rstd * gw[j] + bw[j];
    if (do_gelu) o = gelu_f(o);
    hout[row * HH + j] = o + hin[row * HH + j];
}

__global__ void segmax_kernel(const float* __restrict__ hin, float* __restrict__ vp) {
    int idx = blockIdx.x * 256 + threadIdx.x;              // GG*HH items
    int g = idx >> 8;
    int j = idx & (HH - 1);
    const float* base = hin + (size_t)g * NP * HH + j;
    float m = base[0];
    #pragma unroll
    for (int t = 1; t < NP; t++) m = fmaxf(m, base[(size_t)t * HH]);
    vp[idx] = m;
}

__global__ void segsum_kernel(const float* __restrict__ h, float* __restrict__ o) {
    int idx = blockIdx.x * 256 + threadIdx.x;              // GG*HH items
    int g = idx >> 8;
    int j = idx & (HH - 1);
    const float* base = h + (size_t)g * NP * HH + j;
    float s = 0.f;
    #pragma unroll
    for (int t = 0; t < NP; t++) s += base[(size_t)t * HH];
    o[idx] = s;
}

__global__ void vnadd_kernel(float* __restrict__ vn, const float* __restrict__ t) {
    int idx = blockIdx.x * 256 + threadIdx.x;
    vn[idx] += t[idx];
}

__global__ void l2norm_kernel(float* __restrict__ z) {
    size_t row = blockIdx.x;
    int j = threadIdx.x;
    float v = z[row * HH + j];
    float s = v * v, dummy = 0.f;
    block_reduce2(s, dummy);
    z[row * HH + j] = v * rsqrtf(s);
}

// ---------------- host orchestration -----------------------------------------
extern "C" void kernel_launch(void* const* d_in, const int* in_sizes, int n_in,
                              void* d_out, int out_size) {
    const int*   x        = (const int*)  d_in[0];
    const int*   eidx     = (const int*)  d_in[1];
    const int*   eattr    = (const int*)  d_in[2];
    const int*   batch    = (const int*)  d_in[3];
    const float* atom_emb = (const float*)d_in[4];
    const float* vn_emb   = (const float*)d_in[5];
    const float* bond_emb = (const float*)d_in[6];
    const float* epsv     = (const float*)d_in[7];
    const float* c_w1  = (const float*)d_in[8];
    const float* c_b1  = (const float*)d_in[9];
    const float* c_lng = (const float*)d_in[10];
    const float* c_lnb = (const float*)d_in[11];
    const float* c_w2  = (const float*)d_in[12];
    const float* c_b2  = (const float*)d_in[13];
    const float* n_g   = (const float*)d_in[14];
    const float* n_b   = (const float*)d_in[15];
    const float* v_w1  = (const float*)d_in[16];
    const float* v_b1  = (const float*)d_in[17];
    const float* v_lng = (const float*)d_in[18];
    const float* v_lnb = (const float*)d_in[19];
    const float* v_w2  = (const float*)d_in[20];
    const float* v_b2  = (const float*)d_in[21];
    const float* p_w1  = (const float*)d_in[22];
    const float* p_b1  = (const float*)d_in[23];
    const float* p_lng = (const float*)d_in[24];
    const float* p_lnb = (const float*)d_in[25];
    const float* p_w2  = (const float*)d_in[26];
    const float* p_b2  = (const float*)d_in[27];
    float* out = (float*)d_out;

    float *h, *hin, *aggr, *hid, *vn, *vp, *gh, *t;
    cudaGetSymbolAddress((void**)&h,    g_h);
    cudaGetSymbolAddress((void**)&hin,  g_hin);
    cudaGetSymbolAddress((void**)&aggr, g_aggr);
    cudaGetSymbolAddress((void**)&hid,  g_hid);
    cudaGetSymbolAddress((void**)&vn,   g_vn);
    cudaGetSymbolAddress((void**)&vp,   g_vp);
    cudaGetSymbolAddress((void**)&gh,   g_gh);
    cudaGetSymbolAddress((void**)&t,    g_t);

    const int* src = eidx;
    const int* dst = eidx + EE;

    const int nodeBlocks  = NN * 64 / 256;   // 50000
    const int edgeBlocks  = EE * 64 / 256;   // 100000
    const int gBlocks     = GG * HH / 256;   // 8000
    const dim3 gemmN1(H4 / 128, (NN + 127) / 128);
    const dim3 gemmN2(HH / 128, (NN + 127) / 128);
    const dim3 gemmG1(H4 / 128, (GG + 127) / 128);
    const dim3 gemmG2(HH / 128, (GG + 127) / 128);

    init_h_kernel<<<nodeBlocks, 256>>>(x, atom_emb, h);
    init_vn_kernel<<<gBlocks, 256>>>(vn_emb, vn);

    for (int l = 0; l < LL; l++) {
        addvn_kernel<<<nodeBlocks, 256>>>(vn, batch, h, hin, aggr);
        edge_kernel<<<edgeBlocks, 256>>>(src, dst, eattr,
                                         bond_emb + (size_t)l * 5 * HH, h, aggr);
        // hid = ((1+eps)*h + aggr) @ c_w1 + b1
        gemm_tc_kernel<<<gemmN1, 128>>>(h, aggr, epsv, l,
                                        c_w1 + (size_t)l * HH * H4,
                                        c_b1 + (size_t)l * H4, hid, NN, H4, HH);
        ln_act_kernel<<<NN, 256>>>(hid, c_lng + (size_t)l * H4,
                                   c_lnb + (size_t)l * H4, hid, H4, 1);
        // aggr(reused) = hid @ c_w2 + b2
        gemm_tc_kernel<<<gemmN2, 128>>>(hid, nullptr, nullptr, 0,
                                        c_w2 + (size_t)l * H4 * HH,
                                        c_b2 + (size_t)l * HH, aggr, NN, HH, H4);
        ln_res_kernel<<<NN, 256>>>(aggr, n_g + (size_t)l * HH,
                                   n_b + (size_t)l * HH, hin, h,
                                   (l < LL - 1) ? 1 : 0);
        if (l < LL - 1) {
            segmax_kernel<<<gBlocks, 256>>>(hin, vp);
            gemm_tc_kernel<<<gemmG1, 128>>>(vp, nullptr, nullptr, 0,
                                            v_w1 + (size_t)l * HH * H4,
                                            v_b1 + (size_t)l * H4, gh, GG, H4, HH);
            ln_act_kernel<<<GG, 256>>>(gh, v_lng + (size_t)l * H4,
                                       v_lnb + (size_t)l * H4, gh, H4, 1);
            gemm_tc_kernel<<<gemmG2, 128>>>(gh, nullptr, nullptr, 0,
                                            v_w2 + (size_t)l * H4 * HH,
                                            v_b2 + (size_t)l * HH, t, GG, HH, H4);
            vnadd_kernel<<<gBlocks, 256>>>(vn, t);
        }
    }

    segsum_kernel<<<gBlocks, 256>>>(h, vp);                 // vp reused as h_graph
    gemm_tc_kernel<<<gemmG2, 128>>>(vp, nullptr, nullptr, 0, p_w1, p_b1, t, GG, HH, HH);
    ln_act_kernel<<<GG, 256>>>(t, p_lng, p_lnb, t, HH, 1);
    gemm_tc_kernel<<<gemmG2, 128>>>(t, nullptr, nullptr, 0, p_w2, p_b2, out, GG, HH, HH);
    l2norm_kernel<<<GG, 256>>>(out);
}

// round 3
// speedup vs baseline: 3.0532x; 1.4334x over previous
#include <cuda_runtime.h>
#include <cuda_bf16.h>
#include <math.h>

#define NN 200000
#define EE 400000
#define GG 8000
#define HH 256
#define H4 1024
#define LL 5
#define NP 25   // nodes per graph = NN/GG

// ---------------- scratch (device globals; no allocations allowed) ----------
__device__ float g_h   [(size_t)NN * HH];
__device__ float g_aggr[(size_t)NN * HH];
__device__ float g_o   [(size_t)NN * HH];   // GEMM2 raw output
__device__ float g_hid [(size_t)NN * H4];
__device__ float g_vn  [(size_t)GG * HH];
__device__ float g_vp  [(size_t)GG * HH];
__device__ float g_gh  [(size_t)GG * H4];
__device__ float g_t   [(size_t)GG * HH];

// ---------------- helpers ----------------------------------------------------
__device__ __forceinline__ float gelu_f(float x) {
    return 0.5f * x * (1.0f + erff(x * 0.70710678118654752f));
}

__device__ __forceinline__ unsigned cvt_tf32(float x) {
    unsigned u;
    asm("cvt.rna.tf32.f32 %0, %1;" : "=r"(u) : "f"(x));
    return u;
}

__device__ __forceinline__ void cp16(unsigned d, const void* s, bool pred) {
    asm volatile("cp.async.cg.shared.global [%0], [%1], 16, %2;"
                 :: "r"(d), "l"(s), "r"(pred ? 16u : 0u));
}
__device__ __forceinline__ void cp_commit() {
    asm volatile("cp.async.commit_group;");
}
__device__ __forceinline__ void cp_wait0() {
    asm volatile("cp.async.wait_group 0;");
}

__device__ __forceinline__ void block_reduce2(float& s, float& ss) {
    __shared__ float r1[8], r2[8], fin[2];
    #pragma unroll
    for (int o = 16; o > 0; o >>= 1) {
        s  += __shfl_down_sync(0xffffffffu, s,  o);
        ss += __shfl_down_sync(0xffffffffu, ss, o);
    }
    int w = threadIdx.x >> 5, l = threadIdx.x & 31;
    if (l == 0) { r1[w] = s; r2[w] = ss; }
    __syncthreads();
    if (threadIdx.x < 32) {
        float a = (threadIdx.x < 8) ? r1[threadIdx.x] : 0.f;
        float b = (threadIdx.x < 8) ? r2[threadIdx.x] : 0.f;
        #pragma unroll
        for (int o = 4; o > 0; o >>= 1) {
            a += __shfl_down_sync(0xffffffffu, a, o);
            b += __shfl_down_sync(0xffffffffu, b, o);
        }
        if (threadIdx.x == 0) { fin[0] = a; fin[1] = b; }
    }
    __syncthreads();
    s = fin[0]; ss = fin[1];
}

// ---------------- elementwise kernels -----------------------------------------

__global__ void init_h_kernel(const int* __restrict__ x,
                              const float* __restrict__ emb,
                              float* __restrict__ h) {
    size_t idx = (size_t)blockIdx.x * 256 + threadIdx.x;   // NN*64 items
    int i = (int)(idx >> 6);
    int c = (int)(idx & 63) << 2;
    int a = x[i];
    *(float4*)(h + (size_t)i * HH + c) = *(const float4*)(emb + (size_t)a * HH + c);
}

__global__ void init_vn_kernel(const float* __restrict__ vn_emb,
                               float* __restrict__ vn) {
    int idx = blockIdx.x * 256 + threadIdx.x;              // GG*HH items
    vn[idx] = vn_emb[idx & (HH - 1)];
}

// layer-0 only: h += vn[batch]; aggr = 0
__global__ void addvn_kernel(const float* __restrict__ vn,
                             const int* __restrict__ batch,
                             float* __restrict__ h,
                             float* __restrict__ aggr) {
    size_t idx = (size_t)blockIdx.x * 256 + threadIdx.x;   // NN*64 items
    int i = (int)(idx >> 6);
    int c = (int)(idx & 63) << 2;
    int g = batch[i];
    float4 hv = *(float4*)(h + (size_t)i * HH + c);
    float4 vv = *(const float4*)(vn + (size_t)g * HH + c);
    hv.x += vv.x; hv.y += vv.y; hv.z += vv.z; hv.w += vv.w;
    *(float4*)(h    + (size_t)i * HH + c) = hv;
    *(float4*)(aggr + (size_t)i * HH + c) = make_float4(0.f, 0.f, 0.f, 0.f);
}

// per edge: aggr[dst] += gelu(h[src] + bond[attr])
__global__ void edge_kernel(const int* __restrict__ src,
                            const int* __restrict__ dst,
                            const int* __restrict__ attr,
                            const float* __restrict__ bond,
                            const float* __restrict__ h,
                            float* __restrict__ aggr) {
    size_t idx = (size_t)blockIdx.x * 256 + threadIdx.x;   // EE*64 items
    int e = (int)(idx >> 6);
    int c = (int)(idx & 63) << 2;
    int s = __ldg(src + e), d = __ldg(dst + e), a = __ldg(attr + e);
    float4 hv = *(const float4*)(h + (size_t)s * HH + c);
    float4 bv = *(const float4*)(bond + (size_t)a * HH + c);
    float4 m;
    m.x = gelu_f(hv.x + bv.x);
    m.y = gelu_f(hv.y + bv.y);
    m.z = gelu_f(hv.z + bv.z);
    m.w = gelu_f(hv.w + bv.w);
    float* p = aggr + (size_t)d * HH + c;
    atomicAdd(p + 0, m.x);
    atomicAdd(p + 1, m.y);
    atomicAdd(p + 2, m.z);
    atomicAdd(p + 3, m.w);
}

// ---------------- pipelined TF32 tensor-core GEMM ----------------------------
// C[M,Nn] = A_eff[M,K] @ B[K,Nn] + bias.
// FUSE: A_eff = (1+eps)*A + A2 (A path via LDG/STS); else cp.async for A too.
// Block 128x128, BK=16, 2 stages, 256 threads (8 warps), warp tile 64x32.
#define APITCH 20
#define BPITCH 132
#define ASZ (128 * APITCH)
#define BSZ (16 * BPITCH)

template<bool FUSE>
__global__ void __launch_bounds__(256)
gemm_tc(const float* __restrict__ A, const float* __restrict__ A2,
        const float* __restrict__ eps_ptr, int eps_idx,
        const float* __restrict__ B, const float* __restrict__ bias,
        float* __restrict__ C, int M, int Nn, int K) {
    __shared__ float As[2][ASZ];
    __shared__ float Bs[2][BSZ];

    const int tid  = threadIdx.x;
    const int lane = tid & 31;
    const int warp = tid >> 5;
    const int wm   = (warp >> 2) * 64;   // 2 warps in M
    const int wn   = (warp & 3) * 32;    // 4 warps in N
    const int qr   = lane >> 2;          // 0..7
    const int qc   = lane & 3;           // 0..3

    const int row0 = blockIdx.y * 128;
    const int col0 = blockIdx.x * 128;

    float alpha = 1.0f;
    if (FUSE) alpha = 1.0f + __ldg(&eps_ptr[eps_idx]);

    // per-thread load coords (A: 2 x float4; B: 2 x float4)
    const int ar0 = tid >> 2,          ac0 = (tid & 3) << 2;
    const int ar1 = (tid + 256) >> 2,  ac1 = ((tid + 256) & 3) << 2;
    const int bk0 = tid >> 5,          bn0 = (tid & 31) << 2;
    const int bk1 = (tid + 256) >> 5,  bn1 = ((tid + 256) & 31) << 2;

    unsigned sA[2], sB[2];
    sA[0] = (unsigned)__cvta_generic_to_shared(&As[0][0]);
    sA[1] = (unsigned)__cvta_generic_to_shared(&As[1][0]);
    sB[0] = (unsigned)__cvta_generic_to_shared(&Bs[0][0]);
    sB[1] = (unsigned)__cvta_generic_to_shared(&Bs[1][0]);

    float acc[4][4][4];
    #pragma unroll
    for (int mi = 0; mi < 4; mi++)
        #pragma unroll
        for (int ni = 0; ni < 4; ni++)
            #pragma unroll
            for (int r = 0; r < 4; r++) acc[mi][ni][r] = 0.f;

    float4 va0, va1, wa0, wa1;   // FUSE staging regs

    auto issueB = [&](int kt, int st) {
        cp16(sB[st] + (unsigned)(bk0 * BPITCH + bn0) * 4,
             B + (size_t)(kt + bk0) * Nn + col0 + bn0, true);
        cp16(sB[st] + (unsigned)(bk1 * BPITCH + bn1) * 4,
             B + (size_t)(kt + bk1) * Nn + col0 + bn1, true);
    };
    auto issueA = [&](int kt, int st) {
        cp16(sA[st] + (unsigned)(ar0 * APITCH + ac0) * 4,
             A + (size_t)(row0 + ar0) * K + kt + ac0, row0 + ar0 < M);
        cp16(sA[st] + (unsigned)(ar1 * APITCH + ac1) * 4,
             A + (size_t)(row0 + ar1) * K + kt + ac1, row0 + ar1 < M);
    };
    auto ldgA = [&](int kt) {
        va0 = make_float4(0.f, 0.f, 0.f, 0.f); wa0 = va0; va1 = va0; wa1 = va0;
        if (row0 + ar0 < M) {
            va0 = *(const float4*)(A  + (size_t)(row0 + ar0) * K + kt + ac0);
            wa0 = *(const float4*)(A2 + (size_t)(row0 + ar0) * K + kt + ac0);
        }
        if (row0 + ar1 < M) {
            va1 = *(const float4*)(A  + (size_t)(row0 + ar1) * K + kt + ac1);
            wa1 = *(const float4*)(A2 + (size_t)(row0 + ar1) * K + kt + ac1);
        }
    };
    auto stsA = [&](int st) {
        float4 t0, t1;
        t0.x = fmaf(alpha, va0.x, wa0.x); t0.y = fmaf(alpha, va0.y, wa0.y);
        t0.z = fmaf(alpha, va0.z, wa0.z); t0.w = fmaf(alpha, va0.w, wa0.w);
        t1.x = fmaf(alpha, va1.x, wa1.x); t1.y = fmaf(alpha, va1.y, wa1.y);
        t1.z = fmaf(alpha, va1.z, wa1.z); t1.w = fmaf(alpha, va1.w, wa1.w);
        *(float4*)&As[st][ar0 * APITCH + ac0] = t0;
        *(float4*)&As[st][ar1 * APITCH + ac1] = t1;
    };

    // ---- prologue: fill stage 0 ----
    if (FUSE) ldgA(0); else issueA(0, 0);
    issueB(0, 0);
    cp_commit();
    if (FUSE) stsA(0);
    cp_wait0();
    __syncthreads();

    const int nt = K >> 4;
    int cur = 0;
    for (int t = 0; t < nt; t++) {
        const bool more = (t + 1) < nt;
        const int nxt = cur ^ 1;
        if (more) {
            if (FUSE) ldgA((t + 1) << 4); else issueA((t + 1) << 4, nxt);
            issueB((t + 1) << 4, nxt);
            cp_commit();
        }
        // ---- compute on stage cur ----
        const float* as = As[cur];
        const float* bs = Bs[cur];
        #pragma unroll
        for (int ks = 0; ks < 2; ks++) {
            const int ko = ks * 8;
            unsigned af[4][4];
            #pragma unroll
            for (int mi = 0; mi < 4; mi++) {
                int base = (wm + mi * 16 + qr) * APITCH + ko + qc;
                af[mi][0] = cvt_tf32(as[base]);
                af[mi][1] = cvt_tf32(as[base + 8 * APITCH]);
                af[mi][2] = cvt_tf32(as[base + 4]);
                af[mi][3] = cvt_tf32(as[base + 8 * APITCH + 4]);
            }
            unsigned bf[4][2];
            #pragma unroll
            for (int ni = 0; ni < 4; ni++) {
                int nb = (ko + qc) * BPITCH + wn + ni * 8 + qr;
                bf[ni][0] = cvt_tf32(bs[nb]);
                bf[ni][1] = cvt_tf32(bs[nb + 4 * BPITCH]);
            }
            #pragma unroll
            for (int mi = 0; mi < 4; mi++)
                #pragma unroll
                for (int ni = 0; ni < 4; ni++) {
                    asm volatile(
                        "mma.sync.aligned.m16n8k8.row.col.f32.tf32.tf32.f32 "
                        "{%0,%1,%2,%3}, {%4,%5,%6,%7}, {%8,%9}, {%0,%1,%2,%3};"
                        : "+f"(acc[mi][ni][0]), "+f"(acc[mi][ni][1]),
                          "+f"(acc[mi][ni][2]), "+f"(acc[mi][ni][3])
                        : "r"(af[mi][0]), "r"(af[mi][1]),
                          "r"(af[mi][2]), "r"(af[mi][3]),
                          "r"(bf[ni][0]), "r"(bf[ni][1]));
                }
        }
        if (more) {
            if (FUSE) stsA(nxt);
            cp_wait0();
            __syncthreads();
            cur = nxt;
        }
    }

    // ---- epilogue ----
    #pragma unroll
    for (int mi = 0; mi < 4; mi++) {
        int r0 = row0 + wm + mi * 16 + qr;
        int r1 = r0 + 8;
        #pragma unroll
        for (int ni = 0; ni < 4; ni++) {
            int cc = col0 + wn + ni * 8 + qc * 2;
            float2 bv = *(const float2*)(bias + cc);
            if (r0 < M) {
                float2 o = make_float2(acc[mi][ni][0] + bv.x, acc[mi][ni][1] + bv.y);
                *(float2*)(C + (size_t)r0 * Nn + cc) = o;
            }
            if (r1 < M) {
                float2 o = make_float2(acc[mi][ni][2] + bv.x, acc[mi][ni][3] + bv.y);
                *(float2*)(C + (size_t)r1 * Nn + cc) = o;
            }
        }
    }
}

// row-wise LayerNorm + exact gelu, vectorized (float4/thread). One block per row.
__global__ void ln_act_kernel(const float* __restrict__ in,
                              const float* __restrict__ gw,
                              const float* __restrict__ bw,
                              float* __restrict__ out, int W, int do_gelu) {
    size_t row = blockIdx.x;
    int j = threadIdx.x * 4;
    bool act = j < W;
    float4 v = make_float4(0.f, 0.f, 0.f, 0.f);
    if (act) v = *(const float4*)(in + row * W + j);
    float s = v.x + v.y + v.z + v.w;
    float ss = v.x * v.x + v.y * v.y + v.z * v.z + v.w * v.w;
    block_reduce2(s, ss);
    float m = s / (float)W;
    float rstd = rsqrtf(ss / (float)W - m * m + 1e-5f);
    if (act) {
        float4 g = *(const float4*)(gw + j);
        float4 b = *(const float4*)(bw + j);
        float4 o;
        o.x = (v.x - m) * rstd * g.x + b.x;
        o.y = (v.y - m) * rstd * g.y + b.y;
        o.z = (v.z - m) * rstd * g.z + b.z;
        o.w = (v.w - m) * rstd * g.w + b.w;
        if (do_gelu) {
            o.x = gelu_f(o.x); o.y = gelu_f(o.y);
            o.z = gelu_f(o.z); o.w = gelu_f(o.w);
        }
        *(float4*)(out + row * W + j) = o;
    }
}

// h_new = gelu?(LN(t2)) + h_old  [+ vn_next[batch]];  hin==h; optional aggr=0
__global__ void ln_res_fused_kernel(const float* __restrict__ t2,
                                    const float* __restrict__ gw,
                                    const float* __restrict__ bw,
                                    const float* __restrict__ vn,   // null on last layer
                                    const int* __restrict__ batch,
                                    float* __restrict__ h,
                                    float* __restrict__ aggr,
                                    int do_gelu) {
    size_t row = blockIdx.x;
    int j = threadIdx.x;
    size_t idx = row * HH + j;
    float v = t2[idx];
    float s = v, ss = v * v;
    block_reduce2(s, ss);
    float m = s * (1.f / HH);
    float rstd = rsqrtf(ss * (1.f / HH) - m * m + 1e-5f);
    float o = (v - m) * rstd * gw[j] + bw[j];
    if (do_gelu) o = gelu_f(o);
    o += h[idx];
    if (vn) {
        int g = batch[row];
        o += vn[(size_t)g * HH + j];
        aggr[idx] = 0.f;
    }
    h[idx] = o;
}

__global__ void segmax_kernel(const float* __restrict__ hin, float* __restrict__ vp) {
    int idx = blockIdx.x * 256 + threadIdx.x;              // GG*HH items
    int g = idx >> 8;
    int j = idx & (HH - 1);
    const float* base = hin + (size_t)g * NP * HH + j;
    float m = base[0];
    #pragma unroll
    for (int t = 1; t < NP; t++) m = fmaxf(m, base[(size_t)t * HH]);
    vp[idx] = m;
}

__global__ void segsum_kernel(const float* __restrict__ h, float* __restrict__ o) {
    int idx = blockIdx.x * 256 + threadIdx.x;              // GG*HH items
    int g = idx >> 8;
    int j = idx & (HH - 1);
    const float* base = h + (size_t)g * NP * HH + j;
    float s = 0.f;
    #pragma unroll
    for (int t = 0; t < NP; t++) s += base[(size_t)t * HH];
    o[idx] = s;
}

__global__ void vnadd_kernel(float* __restrict__ vn, const float* __restrict__ t) {
    int idx = blockIdx.x * 256 + threadIdx.x;
    vn[idx] += t[idx];
}

__global__ void l2norm_kernel(float* __restrict__ z) {
    size_t row = blockIdx.x;
    int j = threadIdx.x;
    float v = z[row * HH + j];
    float s = v * v, dummy = 0.f;
    block_reduce2(s, dummy);
    z[row * HH + j] = v * rsqrtf(s);
}

// ---------------- host orchestration -----------------------------------------
extern "C" void kernel_launch(void* const* d_in, const int* in_sizes, int n_in,
                              void* d_out, int out_size) {
    const int*   x        = (const int*)  d_in[0];
    const int*   eidx     = (const int*)  d_in[1];
    const int*   eattr    = (const int*)  d_in[2];
    const int*   batch    = (const int*)  d_in[3];
    const float* atom_emb = (const float*)d_in[4];
    const float* vn_emb   = (const float*)d_in[5];
    const float* bond_emb = (const float*)d_in[6];
    const float* epsv     = (const float*)d_in[7];
    const float* c_w1  = (const float*)d_in[8];
    const float* c_b1  = (const float*)d_in[9];
    const float* c_lng = (const float*)d_in[10];
    const float* c_lnb = (const float*)d_in[11];
    const float* c_w2  = (const float*)d_in[12];
    const float* c_b2  = (const float*)d_in[13];
    const float* n_g   = (const float*)d_in[14];
    const float* n_b   = (const float*)d_in[15];
    const float* v_w1  = (const float*)d_in[16];
    const float* v_b1  = (const float*)d_in[17];
    const float* v_lng = (const float*)d_in[18];
    const float* v_lnb = (const float*)d_in[19];
    const float* v_w2  = (const float*)d_in[20];
    const float* v_b2  = (const float*)d_in[21];
    const float* p_w1  = (const float*)d_in[22];
    const float* p_b1  = (const float*)d_in[23];
    const float* p_lng = (const float*)d_in[24];
    const float* p_lnb = (const float*)d_in[25];
    const float* p_w2  = (const float*)d_in[26];
    const float* p_b2  = (const float*)d_in[27];
    float* out = (float*)d_out;

    float *h, *aggr, *o, *hid, *vn, *vp, *gh, *t;
    cudaGetSymbolAddress((void**)&h,    g_h);
    cudaGetSymbolAddress((void**)&aggr, g_aggr);
    cudaGetSymbolAddress((void**)&o,    g_o);
    cudaGetSymbolAddress((void**)&hid,  g_hid);
    cudaGetSymbolAddress((void**)&vn,   g_vn);
    cudaGetSymbolAddress((void**)&vp,   g_vp);
    cudaGetSymbolAddress((void**)&gh,   g_gh);
    cudaGetSymbolAddress((void**)&t,    g_t);

    const int* src = eidx;
    const int* dst = eidx + EE;

    const int nodeBlocks = NN * 64 / 256;   // 50000
    const int edgeBlocks = EE * 64 / 256;   // 100000
    const int gBlocks    = GG * HH / 256;   // 8000
    const dim3 gemmN1(H4 / 128, (NN + 127) / 128);
    const dim3 gemmN2(HH / 128, (NN + 127) / 128);
    const dim3 gemmG1(H4 / 128, (GG + 127) / 128);
    const dim3 gemmG2(HH / 128, (GG + 127) / 128);

    init_h_kernel<<<nodeBlocks, 256>>>(x, atom_emb, h);
    init_vn_kernel<<<gBlocks, 256>>>(vn_emb, vn);
    addvn_kernel<<<nodeBlocks, 256>>>(vn, batch, h, aggr);   // layer 0 prologue

    for (int l = 0; l < LL; l++) {
        edge_kernel<<<edgeBlocks, 256>>>(src, dst, eattr,
                                         bond_emb + (size_t)l * 5 * HH, h, aggr);
        // hid = ((1+eps)*h + aggr) @ c_w1 + b1
        gemm_tc<true><<<gemmN1, 256>>>(h, aggr, epsv, l,
                                       c_w1 + (size_t)l * HH * H4,
                                       c_b1 + (size_t)l * H4, hid, NN, H4, HH);
        ln_act_kernel<<<NN, 256>>>(hid, c_lng + (size_t)l * H4,
                                   c_lnb + (size_t)l * H4, hid, H4, 1);
        // o = hid @ c_w2 + b2
        gemm_tc<false><<<gemmN2, 256>>>(hid, nullptr, nullptr, 0,
                                        c_w2 + (size_t)l * H4 * HH,
                                        c_b2 + (size_t)l * HH, o, NN, HH, H4);
        if (l < LL - 1) {
            // virtual-node update (uses h == h_in of this layer, still intact)
            segmax_kernel<<<gBlocks, 256>>>(h, vp);
            gemm_tc<false><<<gemmG1, 256>>>(vp, nullptr, nullptr, 0,
                                            v_w1 + (size_t)l * HH * H4,
                                            v_b1 + (size_t)l * H4, gh, GG, H4, HH);
            ln_act_kernel<<<GG, 256>>>(gh, v_lng + (size_t)l * H4,
                                       v_lnb + (size_t)l * H4, gh, H4, 1);
            gemm_tc<false><<<gemmG2, 256>>>(gh, nullptr, nullptr, 0,
                                            v_w2 + (size_t)l * H4 * HH,
                                            v_b2 + (size_t)l * HH, t, GG, HH, H4);
            vnadd_kernel<<<gBlocks, 256>>>(vn, t);
            // h = gelu(LN(o)) + h + vn_next[batch]; aggr = 0
            ln_res_fused_kernel<<<NN, 256>>>(o, n_g + (size_t)l * HH,
                                             n_b + (size_t)l * HH,
                                             vn, batch, h, aggr, 1);
        } else {
            ln_res_fused_kernel<<<NN, 256>>>(o, n_g + (size_t)l * HH,
                                             n_b + (size_t)l * HH,
                                             nullptr, batch, h, aggr, 0);
        }
    }

    segsum_kernel<<<gBlocks, 256>>>(h, vp);                 // vp = h_graph
    gemm_tc<false><<<gemmG2, 256>>>(vp, nullptr, nullptr, 0, p_w1, p_b1, t, GG, HH, HH);
    ln_act_kernel<<<GG, 256>>>(t, p_lng, p_lnb, t, HH, 1);
    gemm_tc<false><<<gemmG2, 256>>>(t, nullptr, nullptr, 0, p_w2, p_b2, out, GG, HH, HH);
    l2norm_kernel<<<GG, 256>>>(out);
}

// round 4
// speedup vs baseline: 3.0912x; 1.0124x over previous
#include <cuda_runtime.h>
#include <cuda_bf16.h>
#include <math.h>

#define NN 200000
#define EE 400000
#define GG 8000
#define HH 256
#define H4 1024
#define LL 5
#define NP 25   // nodes per graph = NN/GG

// ---------------- scratch (device globals; no allocations allowed) ----------
__device__ float g_h   [(size_t)NN * HH];
__device__ float g_aggr[(size_t)NN * HH];
__device__ float g_o   [(size_t)NN * HH];   // GEMM2 raw output
__device__ float g_hid [(size_t)NN * H4];
__device__ float g_vn  [(size_t)GG * HH];
__device__ float g_vp  [(size_t)GG * HH];
__device__ float g_gh  [(size_t)GG * H4];
__device__ float g_t   [(size_t)GG * HH];

// tf32-preconverted weights
#define OFF_CW1 0
#define OFF_CW2 (OFF_CW1 + LL * HH * H4)
#define OFF_VW1 (OFF_CW2 + LL * H4 * HH)
#define OFF_VW2 (OFF_VW1 + (LL - 1) * HH * H4)
#define OFF_PW1 (OFF_VW2 + (LL - 1) * H4 * HH)
#define OFF_PW2 (OFF_PW1 + HH * HH)
#define WT_TOTAL (OFF_PW2 + HH * HH)
__device__ float g_wt[WT_TOTAL];

// ---------------- helpers ----------------------------------------------------
__device__ __forceinline__ float gelu_f(float x) {
    return 0.5f * x * (1.0f + erff(x * 0.70710678118654752f));
}

__device__ __forceinline__ unsigned cvt_tf32(float x) {
    unsigned u;
    asm("cvt.rna.tf32.f32 %0, %1;" : "=r"(u) : "f"(x));
    return u;
}
__device__ __forceinline__ float rnd_tf32(float x) {
    return __uint_as_float(cvt_tf32(x));
}

__device__ __forceinline__ void cp16(unsigned d, const void* s, bool pred) {
    asm volatile("cp.async.cg.shared.global [%0], [%1], 16, %2;"
                 :: "r"(d), "l"(s), "r"(pred ? 16u : 0u));
}
__device__ __forceinline__ void cp_commit() {
    asm volatile("cp.async.commit_group;");
}
__device__ __forceinline__ void cp_wait0() {
    asm volatile("cp.async.wait_group 0;");
}

__device__ __forceinline__ void block_reduce2(float& s, float& ss) {
    __shared__ float r1[8], r2[8], fin[2];
    #pragma unroll
    for (int o = 16; o > 0; o >>= 1) {
        s  += __shfl_down_sync(0xffffffffu, s,  o);
        ss += __shfl_down_sync(0xffffffffu, ss, o);
    }
    int w = threadIdx.x >> 5, l = threadIdx.x & 31;
    if (l == 0) { r1[w] = s; r2[w] = ss; }
    __syncthreads();
    if (threadIdx.x < 32) {
        float a = (threadIdx.x < 8) ? r1[threadIdx.x] : 0.f;
        float b = (threadIdx.x < 8) ? r2[threadIdx.x] : 0.f;
        #pragma unroll
        for (int o = 4; o > 0; o >>= 1) {
            a += __shfl_down_sync(0xffffffffu, a, o);
            b += __shfl_down_sync(0xffffffffu, b, o);
        }
        if (threadIdx.x == 0) { fin[0] = a; fin[1] = b; }
    }
    __syncthreads();
    s = fin[0]; ss = fin[1];
}

// ---------------- small kernels ------------------------------------------------

__global__ void cvt_w_kernel(const float* __restrict__ src,
                             float* __restrict__ dst, int n) {
    int i = blockIdx.x * 256 + threadIdx.x;
    if (i < n) dst[i] = rnd_tf32(src[i]);
}

__global__ void init_h_kernel(const int* __restrict__ x,
                              const float* __restrict__ emb,
                              float* __restrict__ h) {
    size_t idx = (size_t)blockIdx.x * 256 + threadIdx.x;   // NN*64 items
    int i = (int)(idx >> 6);
    int c = (int)(idx & 63) << 2;
    int a = x[i];
    *(float4*)(h + (size_t)i * HH + c) = *(const float4*)(emb + (size_t)a * HH + c);
}

__global__ void init_vn_kernel(const float* __restrict__ vn_emb,
                               float* __restrict__ vn) {
    int idx = blockIdx.x * 256 + threadIdx.x;              // GG*HH items
    vn[idx] = vn_emb[idx & (HH - 1)];
}

// layer-0 only: h += vn[batch]; aggr = 0
__global__ void addvn_kernel(const float* __restrict__ vn,
                             const int* __restrict__ batch,
                             float* __restrict__ h,
                             float* __restrict__ aggr) {
    size_t idx = (size_t)blockIdx.x * 256 + threadIdx.x;   // NN*64 items
    int i = (int)(idx >> 6);
    int c = (int)(idx & 63) << 2;
    int g = batch[i];
    float4 hv = *(float4*)(h + (size_t)i * HH + c);
    float4 vv = *(const float4*)(vn + (size_t)g * HH + c);
    hv.x += vv.x; hv.y += vv.y; hv.z += vv.z; hv.w += vv.w;
    *(float4*)(h    + (size_t)i * HH + c) = hv;
    *(float4*)(aggr + (size_t)i * HH + c) = make_float4(0.f, 0.f, 0.f, 0.f);
}

// per edge: aggr[dst] += gelu(h[src] + bond[attr])
__global__ void edge_kernel(const int* __restrict__ src,
                            const int* __restrict__ dst,
                            const int* __restrict__ attr,
                            const float* __restrict__ bond,
                            const float* __restrict__ h,
                            float* __restrict__ aggr) {
    size_t idx = (size_t)blockIdx.x * 256 + threadIdx.x;   // EE*64 items
    int e = (int)(idx >> 6);
    int c = (int)(idx & 63) << 2;
    int s = __ldg(src + e), d = __ldg(dst + e), a = __ldg(attr + e);
    float4 hv = *(const float4*)(h + (size_t)s * HH + c);
    float4 bv = *(const float4*)(bond + (size_t)a * HH + c);
    float4 m;
    m.x = gelu_f(hv.x + bv.x);
    m.y = gelu_f(hv.y + bv.y);
    m.z = gelu_f(hv.z + bv.z);
    m.w = gelu_f(hv.w + bv.w);
    float* p = aggr + (size_t)d * HH + c;
    atomicAdd(p + 0, m.x);
    atomicAdd(p + 1, m.y);
    atomicAdd(p + 2, m.z);
    atomicAdd(p + 3, m.w);
}

// ---------------- pipelined TF32 tensor-core GEMM ----------------------------
// C[M,Nn] = A_eff[M,K] @ B[K,Nn] + bias.  B is PRE-ROUNDED tf32 bits.
// FUSE:  A_eff = (1+eps)*A + A2; cvt at STS. !FUSE: A pre-rounded, cp.async.
// Block 128x128, BK=16, 2 stages, 256 threads (8 warps), warp tile 64x32.
// Mainloop fragments: plain float LDS + free bit-reinterpret (no cvt).
#define APITCH 20
#define BPITCH 132
#define ASZ (128 * APITCH)
#define BSZ (16 * BPITCH)

template<bool FUSE>
__global__ void __launch_bounds__(256)
gemm_tc(const float* __restrict__ A, const float* __restrict__ A2,
        const float* __restrict__ eps_ptr, int eps_idx,
        const float* __restrict__ B, const float* __restrict__ bias,
        float* __restrict__ C, int M, int Nn, int K) {
    __shared__ float As[2][ASZ];
    __shared__ float Bs[2][BSZ];

    const int tid  = threadIdx.x;
    const int lane = tid & 31;
    const int warp = tid >> 5;
    const int wm   = (warp >> 2) * 64;   // 2 warps in M
    const int wn   = (warp & 3) * 32;    // 4 warps in N
    const int qr   = lane >> 2;          // 0..7
    const int qc   = lane & 3;           // 0..3

    const int row0 = blockIdx.y * 128;
    const int col0 = blockIdx.x * 128;

    float alpha = 1.0f;
    if (FUSE) alpha = 1.0f + __ldg(&eps_ptr[eps_idx]);

    const int ar0 = tid >> 2,          ac0 = (tid & 3) << 2;
    const int ar1 = (tid + 256) >> 2,  ac1 = ((tid + 256) & 3) << 2;
    const int bk0 = tid >> 5,          bn0 = (tid & 31) << 2;
    const int bk1 = (tid + 256) >> 5,  bn1 = ((tid + 256) & 31) << 2;

    unsigned sA[2], sB[2];
    sA[0] = (unsigned)__cvta_generic_to_shared(&As[0][0]);
    sA[1] = (unsigned)__cvta_generic_to_shared(&As[1][0]);
    sB[0] = (unsigned)__cvta_generic_to_shared(&Bs[0][0]);
    sB[1] = (unsigned)__cvta_generic_to_shared(&Bs[1][0]);

    float acc[4][4][4];
    #pragma unroll
    for (int mi = 0; mi < 4; mi++)
        #pragma unroll
        for (int ni = 0; ni < 4; ni++)
            #pragma unroll
            for (int r = 0; r < 4; r++) acc[mi][ni][r] = 0.f;

    float4 va0, va1, wa0, wa1;   // FUSE staging regs

    auto issueB = [&](int kt, int st) {
        cp16(sB[st] + (unsigned)(bk0 * BPITCH + bn0) * 4,
             B + (size_t)(kt + bk0) * Nn + col0 + bn0, true);
        cp16(sB[st] + (unsigned)(bk1 * BPITCH + bn1) * 4,
             B + (size_t)(kt + bk1) * Nn + col0 + bn1, true);
    };
    auto issueA = [&](int kt, int st) {
        cp16(sA[st] + (unsigned)(ar0 * APITCH + ac0) * 4,
             A + (size_t)(row0 + ar0) * K + kt + ac0, row0 + ar0 < M);
        cp16(sA[st] + (unsigned)(ar1 * APITCH + ac1) * 4,
             A + (size_t)(row0 + ar1) * K + kt + ac1, row0 + ar1 < M);
    };
    auto ldgA = [&](int kt) {
        va0 = make_float4(0.f, 0.f, 0.f, 0.f); wa0 = va0; va1 = va0; wa1 = va0;
        if (row0 + ar0 < M) {
            va0 = *(const float4*)(A  + (size_t)(row0 + ar0) * K + kt + ac0);
            wa0 = *(const float4*)(A2 + (size_t)(row0 + ar0) * K + kt + ac0);
        }
        if (row0 + ar1 < M) {
            va1 = *(const float4*)(A  + (size_t)(row0 + ar1) * K + kt + ac1);
            wa1 = *(const float4*)(A2 + (size_t)(row0 + ar1) * K + kt + ac1);
        }
    };
    auto stsA = [&](int st) {
        float4 t0, t1;
        t0.x = rnd_tf32(fmaf(alpha, va0.x, wa0.x));
        t0.y = rnd_tf32(fmaf(alpha, va0.y, wa0.y));
        t0.z = rnd_tf32(fmaf(alpha, va0.z, wa0.z));
        t0.w = rnd_tf32(fmaf(alpha, va0.w, wa0.w));
        t1.x = rnd_tf32(fmaf(alpha, va1.x, wa1.x));
        t1.y = rnd_tf32(fmaf(alpha, va1.y, wa1.y));
        t1.z = rnd_tf32(fmaf(alpha, va1.z, wa1.z));
        t1.w = rnd_tf32(fmaf(alpha, va1.w, wa1.w));
        *(float4*)&As[st][ar0 * APITCH + ac0] = t0;
        *(float4*)&As[st][ar1 * APITCH + ac1] = t1;
    };

    // ---- prologue: fill stage 0 ----
    if (FUSE) ldgA(0); else issueA(0, 0);
    issueB(0, 0);
    cp_commit();
    if (FUSE) stsA(0);
    cp_wait0();
    __syncthreads();

    const int nt = K >> 4;
    int cur = 0;
    for (int t = 0; t < nt; t++) {
        const bool more = (t + 1) < nt;
        const int nxt = cur ^ 1;
        if (more) {
            if (FUSE) ldgA((t + 1) << 4); else issueA((t + 1) << 4, nxt);
            issueB((t + 1) << 4, nxt);
            cp_commit();
        }
        // ---- compute on stage cur (no cvt: data pre-rounded) ----
        const float* as = As[cur];
        const float* bs = Bs[cur];
        #pragma unroll
        for (int ks = 0; ks < 2; ks++) {
            const int ko = ks * 8;
            unsigned af[4][4];
            #pragma unroll
            for (int mi = 0; mi < 4; mi++) {
                int base = (wm + mi * 16 + qr) * APITCH + ko + qc;
                af[mi][0] = __float_as_uint(as[base]);
                af[mi][1] = __float_as_uint(as[base + 8 * APITCH]);
                af[mi][2] = __float_as_uint(as[base + 4]);
                af[mi][3] = __float_as_uint(as[base + 8 * APITCH + 4]);
            }
            unsigned bf[4][2];
            #pragma unroll
            for (int ni = 0; ni < 4; ni++) {
                int nb = (ko + qc) * BPITCH + wn + ni * 8 + qr;
                bf[ni][0] = __float_as_uint(bs[nb]);
                bf[ni][1] = __float_as_uint(bs[nb + 4 * BPITCH]);
            }
            #pragma unroll
            for (int mi = 0; mi < 4; mi++)
                #pragma unroll
                for (int ni = 0; ni < 4; ni++) {
                    asm volatile(
                        "mma.sync.aligned.m16n8k8.row.col.f32.tf32.tf32.f32 "
                        "{%0,%1,%2,%3}, {%4,%5,%6,%7}, {%8,%9}, {%0,%1,%2,%3};"
                        : "+f"(acc[mi][ni][0]), "+f"(acc[mi][ni][1]),
                          "+f"(acc[mi][ni][2]), "+f"(acc[mi][ni][3])
                        : "r"(af[mi][0]), "r"(af[mi][1]),
                          "r"(af[mi][2]), "r"(af[mi][3]),
                          "r"(bf[ni][0]), "r"(bf[ni][1]));
                }
        }
        if (more) {
            if (FUSE) stsA(nxt);
            cp_wait0();
            __syncthreads();
            cur = nxt;
        }
    }

    // ---- epilogue ----
    #pragma unroll
    for (int mi = 0; mi < 4; mi++) {
        int r0 = row0 + wm + mi * 16 + qr;
        int r1 = r0 + 8;
        #pragma unroll
        for (int ni = 0; ni < 4; ni++) {
            int cc = col0 + wn + ni * 8 + qc * 2;
            float2 bv = *(const float2*)(bias + cc);
            if (r0 < M) {
                float2 o = make_float2(acc[mi][ni][0] + bv.x, acc[mi][ni][1] + bv.y);
                *(float2*)(C + (size_t)r0 * Nn + cc) = o;
            }
            if (r1 < M) {
                float2 o = make_float2(acc[mi][ni][2] + bv.x, acc[mi][ni][3] + bv.y);
                *(float2*)(C + (size_t)r1 * Nn + cc) = o;
            }
        }
    }
}

// row-wise LayerNorm + exact gelu; OUTPUT IS TF32-ROUNDED (consumed only by GEMMs)
__global__ void ln_act_kernel(const float* __restrict__ in,
                              const float* __restrict__ gw,
                              const float* __restrict__ bw,
                              float* __restrict__ out, int W, int do_gelu) {
    size_t row = blockIdx.x;
    int j = threadIdx.x * 4;
    bool act = j < W;
    float4 v = make_float4(0.f, 0.f, 0.f, 0.f);
    if (act) v = *(const float4*)(in + row * W + j);
    float s = v.x + v.y + v.z + v.w;
    float ss = v.x * v.x + v.y * v.y + v.z * v.z + v.w * v.w;
    block_reduce2(s, ss);
    float m = s / (float)W;
    float rstd = rsqrtf(ss / (float)W - m * m + 1e-5f);
    if (act) {
        float4 g = *(const float4*)(gw + j);
        float4 b = *(const float4*)(bw + j);
        float4 o;
        o.x = (v.x - m) * rstd * g.x + b.x;
        o.y = (v.y - m) * rstd * g.y + b.y;
        o.z = (v.z - m) * rstd * g.z + b.z;
        o.w = (v.w - m) * rstd * g.w + b.w;
        if (do_gelu) {
            o.x = gelu_f(o.x); o.y = gelu_f(o.y);
            o.z = gelu_f(o.z); o.w = gelu_f(o.w);
        }
        o.x = rnd_tf32(o.x); o.y = rnd_tf32(o.y);
        o.z = rnd_tf32(o.z); o.w = rnd_tf32(o.w);
        *(float4*)(out + row * W + j) = o;
    }
}

// h_new = gelu?(LN(t2)) + h_old  [+ vn_next[batch]];  optional aggr=0
__global__ void ln_res_fused_kernel(const float* __restrict__ t2,
                                    const float* __restrict__ gw,
                                    const float* __restrict__ bw,
                                    const float* __restrict__ vn,   // null on last layer
                                    const int* __restrict__ batch,
                                    float* __restrict__ h,
                                    float* __restrict__ aggr,
                                    int do_gelu) {
    size_t row = blockIdx.x;
    int j = threadIdx.x;
    size_t idx = row * HH + j;
    float v = t2[idx];
    float s = v, ss = v * v;
    block_reduce2(s, ss);
    float m = s * (1.f / HH);
    float rstd = rsqrtf(ss * (1.f / HH) - m * m + 1e-5f);
    float o = (v - m) * rstd * gw[j] + bw[j];
    if (do_gelu) o = gelu_f(o);
    o += h[idx];
    if (vn) {
        int g = batch[row];
        o += vn[(size_t)g * HH + j];
        aggr[idx] = 0.f;
    }
    h[idx] = o;
}

// outputs feed GEMM A only -> tf32-rounded
__global__ void segmax_kernel(const float* __restrict__ hin, float* __restrict__ vp) {
    int idx = blockIdx.x * 256 + threadIdx.x;              // GG*HH items
    int g = idx >> 8;
    int j = idx & (HH - 1);
    const float* base = hin + (size_t)g * NP * HH + j;
    float m = base[0];
    #pragma unroll
    for (int t = 1; t < NP; t++) m = fmaxf(m, base[(size_t)t * HH]);
    vp[idx] = rnd_tf32(m);
}

__global__ void segsum_kernel(const float* __restrict__ h, float* __restrict__ o) {
    int idx = blockIdx.x * 256 + threadIdx.x;              // GG*HH items
    int g = idx >> 8;
    int j = idx & (HH - 1);
    const float* base = h + (size_t)g * NP * HH + j;
    float s = 0.f;
    #pragma unroll
    for (int t = 0; t < NP; t++) s += base[(size_t)t * HH];
    o[idx] = rnd_tf32(s);
}

__global__ void vnadd_kernel(float* __restrict__ vn, const float* __restrict__ t) {
    int idx = blockIdx.x * 256 + threadIdx.x;
    vn[idx] += t[idx];
}

__global__ void l2norm_kernel(float* __restrict__ z) {
    size_t row = blockIdx.x;
    int j = threadIdx.x;
    float v = z[row * HH + j];
    float s = v * v, dummy = 0.f;
    block_reduce2(s, dummy);
    z[row * HH + j] = v * rsqrtf(s);
}

// ---------------- host orchestration -----------------------------------------
extern "C" void kernel_launch(void* const* d_in, const int* in_sizes, int n_in,
                              void* d_out, int out_size) {
    const int*   x        = (const int*)  d_in[0];
    const int*   eidx     = (const int*)  d_in[1];
    const int*   eattr    = (const int*)  d_in[2];
    const int*   batch    = (const int*)  d_in[3];
    const float* atom_emb = (const float*)d_in[4];
    const float* vn_emb   = (const float*)d_in[5];
    const float* bond_emb = (const float*)d_in[6];
    const float* epsv     = (const float*)d_in[7];
    const float* c_w1  = (const float*)d_in[8];
    const float* c_b1  = (const float*)d_in[9];
    const float* c_lng = (const float*)d_in[10];
    const float* c_lnb = (const float*)d_in[11];
    const float* c_w2  = (const float*)d_in[12];
    const float* c_b2  = (const float*)d_in[13];
    const float* n_g   = (const float*)d_in[14];
    const float* n_b   = (const float*)d_in[15];
    const float* v_w1  = (const float*)d_in[16];
    const float* v_b1  = (const float*)d_in[17];
    const float* v_lng = (const float*)d_in[18];
    const float* v_lnb = (const float*)d_in[19];
    const float* v_w2  = (const float*)d_in[20];
    const float* v_b2  = (const float*)d_in[21];
    const float* p_w1  = (const float*)d_in[22];
    const float* p_b1  = (const float*)d_in[23];
    const float* p_lng = (const float*)d_in[24];
    const float* p_lnb = (const float*)d_in[25];
    const float* p_w2  = (const float*)d_in[26];
    const float* p_b2  = (const float*)d_in[27];
    float* out = (float*)d_out;

    float *h, *aggr, *o, *hid, *vn, *vp, *gh, *t, *wt;
    cudaGetSymbolAddress((void**)&h,    g_h);
    cudaGetSymbolAddress((void**)&aggr, g_aggr);
    cudaGetSymbolAddress((void**)&o,    g_o);
    cudaGetSymbolAddress((void**)&hid,  g_hid);
    cudaGetSymbolAddress((void**)&vn,   g_vn);
    cudaGetSymbolAddress((void**)&vp,   g_vp);
    cudaGetSymbolAddress((void**)&gh,   g_gh);
    cudaGetSymbolAddress((void**)&t,    g_t);
    cudaGetSymbolAddress((void**)&wt,   g_wt);

    float* cw1t = wt + OFF_CW1;
    float* cw2t = wt + OFF_CW2;
    float* vw1t = wt + OFF_VW1;
    float* vw2t = wt + OFF_VW2;
    float* pw1t = wt + OFF_PW1;
    float* pw2t = wt + OFF_PW2;

    const int* src = eidx;
    const int* dst = eidx + EE;

    const int nodeBlocks = NN * 64 / 256;   // 50000
    const int edgeBlocks = EE * 64 / 256;   // 100000
    const int gBlocks    = GG * HH / 256;   // 8000
    const dim3 gemmN1(H4 / 128, (NN + 127) / 128);
    const dim3 gemmN2(HH / 128, (NN + 127) / 128);
    const dim3 gemmG1(H4 / 128, (GG + 127) / 128);
    const dim3 gemmG2(HH / 128, (GG + 127) / 128);

    // pre-round weights to tf32 (once per call)
    {
        int n1 = LL * HH * H4;          // c_w1 / c_w2
        int n2 = (LL - 1) * HH * H4;    // v_w1 / v_w2
        int n3 = HH * HH;               // p_w1 / p_w2
        cvt_w_kernel<<<(n1 + 255) / 256, 256>>>(c_w1, cw1t, n1);
        cvt_w_kernel<<<(n1 + 255) / 256, 256>>>(c_w2, cw2t, n1);
        cvt_w_kernel<<<(n2 + 255) / 256, 256>>>(v_w1, vw1t, n2);
        cvt_w_kernel<<<(n2 + 255) / 256, 256>>>(v_w2, vw2t, n2);
        cvt_w_kernel<<<(n3 + 255) / 256, 256>>>(p_w1, pw1t, n3);
        cvt_w_kernel<<<(n3 + 255) / 256, 256>>>(p_w2, pw2t, n3);
    }

    init_h_kernel<<<nodeBlocks, 256>>>(x, atom_emb, h);
    init_vn_kernel<<<gBlocks, 256>>>(vn_emb, vn);
    addvn_kernel<<<nodeBlocks, 256>>>(vn, batch, h, aggr);   // layer 0 prologue

    for (int l = 0; l < LL; l++) {
        edge_kernel<<<edgeBlocks, 256>>>(src, dst, eattr,
                                         bond_emb + (size_t)l * 5 * HH, h, aggr);
        // hid = ((1+eps)*h + aggr) @ c_w1 + b1
        gemm_tc<true><<<gemmN1, 256>>>(h, aggr, epsv, l,
                                       cw1t + (size_t)l * HH * H4,
                                       c_b1 + (size_t)l * H4, hid, NN, H4, HH);
        ln_act_kernel<<<NN, 256>>>(hid, c_lng + (size_t)l * H4,
                                   c_lnb + (size_t)l * H4, hid, H4, 1);
        // o = hid @ c_w2 + b2
        gemm_tc<false><<<gemmN2, 256>>>(hid, nullptr, nullptr, 0,
                                        cw2t + (size_t)l * H4 * HH,
                                        c_b2 + (size_t)l * HH, o, NN, HH, H4);
        if (l < LL - 1) {
            // virtual-node update (uses h == h_in of this layer, still intact)
            segmax_kernel<<<gBlocks, 256>>>(h, vp);
            gemm_tc<false><<<gemmG1, 256>>>(vp, nullptr, nullptr, 0,
                                            vw1t + (size_t)l * HH * H4,
                                            v_b1 + (size_t)l * H4, gh, GG, H4, HH);
            ln_act_kernel<<<GG, 256>>>(gh, v_lng + (size_t)l * H4,
                                       v_lnb + (size_t)l * H4, gh, H4, 1);
            gemm_tc<false><<<gemmG2, 256>>>(gh, nullptr, nullptr, 0,
                                            vw2t + (size_t)l * H4 * HH,
                                            v_b2 + (size_t)l * HH, t, GG, HH, H4);
            vnadd_kernel<<<gBlocks, 256>>>(vn, t);
            // h = gelu(LN(o)) + h + vn_next[batch]; aggr = 0
            ln_res_fused_kernel<<<NN, 256>>>(o, n_g + (size_t)l * HH,
                                             n_b + (size_t)l * HH,
                                             vn, batch, h, aggr, 1);
        } else {
            ln_res_fused_kernel<<<NN, 256>>>(o, n_g + (size_t)l * HH,
                                             n_b + (size_t)l * HH,
                                             nullptr, batch, h, aggr, 0);
        }
    }

    segsum_kernel<<<gBlocks, 256>>>(h, vp);                 // vp = h_graph
    gemm_tc<false><<<gemmG2, 256>>>(vp, nullptr, nullptr, 0, pw1t, p_b1, t, GG, HH, HH);
    ln_act_kernel<<<GG, 256>>>(t, p_lng, p_lnb, t, HH, 1);
    gemm_tc<false><<<gemmG2, 256>>>(t, nullptr, nullptr, 0, pw2t, p_b2, out, GG, HH, HH);
    l2norm_kernel<<<GG, 256>>>(out);
}

// round 16
// speedup vs baseline: 3.6141x; 1.1691x over previous
#include <cuda_runtime.h>
#include <cuda_bf16.h>
#include <cuda_fp16.h>
#include <cstdint>
#include <math.h>

#define NN 200000
#define EE 400000
#define GG 8000
#define HH 256
#define H4 1024
#define LL 5
#define NP 25   /* nodes per graph = NN/GG */

/* ---------------- scratch (device globals; no allocations allowed) --------- */
__device__ float  g_h   [(size_t)NN * HH];
__device__ float  g_aggr[(size_t)NN * HH];
__device__ float  g_o   [(size_t)NN * HH];
__device__ float  g_hid [(size_t)NN * H4];   /* GEMM1 raw output (float) */
__device__ __half g_hidh[(size_t)NN * H4];   /* ln_act output (half)     */
__device__ float  g_vn  [(size_t)GG * HH];
__device__ __half g_vph [(size_t)GG * HH];   /* segmax/segsum out (half) */
__device__ float  g_gh  [(size_t)GG * H4];
__device__ __half g_ghh [(size_t)GG * H4];
__device__ float  g_t   [(size_t)GG * HH];
__device__ __half g_th  [(size_t)GG * HH];

/* half, TRANSPOSED weights ([N][K] layout) */
#define OFF_CW1 0
#define OFF_CW2 (OFF_CW1 + LL * HH * H4)
#define OFF_VW1 (OFF_CW2 + LL * H4 * HH)
#define OFF_VW2 (OFF_VW1 + (LL - 1) * HH * H4)
#define OFF_PW1 (OFF_VW2 + (LL - 1) * H4 * HH)
#define OFF_PW2 (OFF_PW1 + HH * HH)
#define WT_TOTAL (OFF_PW2 + HH * HH)
__device__ __half g_wt[WT_TOTAL];

/* ---------------- helpers --------------------------------------------------- */
__device__ __forceinline__ float gelu_f(float x) {
    return 0.5f * x * (1.0f + erff(x * 0.70710678118654752f));
}

__device__ __forceinline__ void cp16(unsigned d, const void* s, bool pred) {
    asm volatile("cp.async.cg.shared.global [%0], [%1], 16, %2;"
                 :: "r"(d), "l"(s), "r"(pred ? 16u : 0u));
}
__device__ __forceinline__ void cp_commit_fn() {
    asm volatile("cp.async.commit_group;");
}
__device__ __forceinline__ void cp_wait0_fn() {
    asm volatile("cp.async.wait_group 0;");
}

__device__ __forceinline__ void block_reduce2(float& s, float& ss) {
    __shared__ float r1[8], r2[8], fin[2];
    #pragma unroll
    for (int o = 16; o > 0; o >>= 1) {
        s  += __shfl_down_sync(0xffffffffu, s,  o);
        ss += __shfl_down_sync(0xffffffffu, ss, o);
    }
    int w = threadIdx.x >> 5, l = threadIdx.x & 31;
    if (l == 0) { r1[w] = s; r2[w] = ss; }
    __syncthreads();
    if (threadIdx.x < 32) {
        float a = (threadIdx.x < 8) ? r1[threadIdx.x] : 0.f;
        float b = (threadIdx.x < 8) ? r2[threadIdx.x] : 0.f;
        #pragma unroll
        for (int o = 4; o > 0; o >>= 1) {
            a += __shfl_down_sync(0xffffffffu, a, o);
            b += __shfl_down_sync(0xffffffffu, b, o);
        }
        if (threadIdx.x == 0) { fin[0] = a; fin[1] = b; }
    }
    __syncthreads();
    s = fin[0]; ss = fin[1];
}

/* ---------------- weight prep: transpose + half convert --------------------- */
/* src: [batch][K][N] float  ->  dst: [batch][N][K] half */
__global__ void transpose_w_kernel(const float* __restrict__ src,
                                   __half* __restrict__ dst, int K, int N) {
    __shared__ float tile[32][33];
    size_t boff = (size_t)blockIdx.z * K * N;
    int k0 = blockIdx.y * 32, n0 = blockIdx.x * 32;
    #pragma unroll
    for (int i = threadIdx.y; i < 32; i += 8)
        tile[i][threadIdx.x] =
            src[boff + (size_t)(k0 + i) * N + n0 + threadIdx.x];
    __syncthreads();
    #pragma unroll
    for (int i = threadIdx.y; i < 32; i += 8)
        dst[boff + (size_t)(n0 + i) * K + k0 + threadIdx.x] =
            __float2half_rn(tile[threadIdx.x][i]);
}

/* ---------------- elementwise kernels --------------------------------------- */
__global__ void init_h_kernel(const int* __restrict__ x,
                              const float* __restrict__ emb,
                              float* __restrict__ h) {
    size_t idx = (size_t)blockIdx.x * 256 + threadIdx.x;
    int i = (int)(idx >> 6);
    int c = (int)(idx & 63) << 2;
    int a = x[i];
    *(float4*)(h + (size_t)i * HH + c) = *(const float4*)(emb + (size_t)a * HH + c);
}

__global__ void init_vn_kernel(const float* __restrict__ vn_emb,
                               float* __restrict__ vn) {
    int idx = blockIdx.x * 256 + threadIdx.x;
    vn[idx] = vn_emb[idx & (HH - 1)];
}

__global__ void addvn_kernel(const float* __restrict__ vn,
                             const int* __restrict__ batch,
                             float* __restrict__ h,
                             float* __restrict__ aggr) {
    size_t idx = (size_t)blockIdx.x * 256 + threadIdx.x;
    int i = (int)(idx >> 6);
    int c = (int)(idx & 63) << 2;
    int g = batch[i];
    float4 hv = *(float4*)(h + (size_t)i * HH + c);
    float4 vv = *(const float4*)(vn + (size_t)g * HH + c);
    hv.x += vv.x; hv.y += vv.y; hv.z += vv.z; hv.w += vv.w;
    *(float4*)(h    + (size_t)i * HH + c) = hv;
    *(float4*)(aggr + (size_t)i * HH + c) = make_float4(0.f, 0.f, 0.f, 0.f);
}

__global__ void edge_kernel(const int* __restrict__ src,
                            const int* __restrict__ dst,
                            const int* __restrict__ attr,
                            const float* __restrict__ bond,
                            const float* __restrict__ h,
                            float* __restrict__ aggr) {
    size_t idx = (size_t)blockIdx.x * 256 + threadIdx.x;
    int e = (int)(idx >> 6);
    int c = (int)(idx & 63) << 2;
    int s = __ldg(src + e), d = __ldg(dst + e), a = __ldg(attr + e);
    float4 hv = *(const float4*)(h + (size_t)s * HH + c);
    float4 bv = *(const float4*)(bond + (size_t)a * HH + c);
    float4 m;
    m.x = gelu_f(hv.x + bv.x);
    m.y = gelu_f(hv.y + bv.y);
    m.z = gelu_f(hv.z + bv.z);
    m.w = gelu_f(hv.w + bv.w);
    float* p = aggr + (size_t)d * HH + c;
    atomicAdd(p + 0, m.x);
    atomicAdd(p + 1, m.y);
    atomicAdd(p + 2, m.z);
    atomicAdd(p + 3, m.w);
}

/* ---------------- fp16 mma.sync GEMM ------------------------------------------
   C[M,Nn] = A_eff[M,K] @ BT[Nn,K]^T     (no bias: folded into consumers)
   fuse!=0: A_eff = half((1+eps)*Af + A2), Af/A2 float via LDG/cvt/STS.
   else:    A = Ah (pre-converted half) via cp.async.
   Block 128x128, BK=32, 2 stages, 256 threads (8 warps), warp tile 64x32,
   mma.sync.m16n8k16.f32.f16.f16.f32.  Smem pitch 40 halves (conflict-free). */
#define HPITCH 40
#define HSZ (128 * HPITCH)

__global__ void __launch_bounds__(256)
gemm16(const float* __restrict__ Af, const float* __restrict__ A2,
       const __half* __restrict__ Ah,
       const float* __restrict__ epsp, int epsi,
       const __half* __restrict__ BT,
       float* __restrict__ C, int M, int Nn, int K, int fuse) {
    __shared__ __half As[2][HSZ];
    __shared__ __half Bs[2][HSZ];

    const int tid  = threadIdx.x;
    const int lane = tid & 31;
    const int warp = tid >> 5;
    const int wm   = (warp >> 2) * 64;   /* 2 warps in M */
    const int wn   = (warp & 3) * 32;    /* 4 warps in N */
    const int qr   = lane >> 2;          /* 0..7 */
    const int qc   = lane & 3;           /* 0..3 */

    const int row0 = blockIdx.y * 128;
    const int col0 = blockIdx.x * 128;

    float alpha = 1.0f;
    if (fuse) alpha = 1.0f + __ldg(&epsp[epsi]);

    unsigned sA[2], sB[2];
    sA[0] = (unsigned)__cvta_generic_to_shared(&As[0][0]);
    sA[1] = (unsigned)__cvta_generic_to_shared(&As[1][0]);
    sB[0] = (unsigned)__cvta_generic_to_shared(&Bs[0][0]);
    sB[1] = (unsigned)__cvta_generic_to_shared(&Bs[1][0]);

    float acc[4][4][4];
    #pragma unroll
    for (int mi = 0; mi < 4; mi++)
        #pragma unroll
        for (int ni = 0; ni < 4; ni++)
            #pragma unroll
            for (int r = 0; r < 4; r++) acc[mi][ni][r] = 0.f;

    float4 va[4], wa[4];   /* fuse staging */

    /* load coords. half path: 2 iters x 16B (8 halves). fuse: 4 iters x float4 */
    auto issueB = [&](int kt, int st) {
        #pragma unroll
        for (int i = 0; i < 2; i++) {
            int g = tid + i * 256;         /* 0..511 */
            int r = g >> 2;                /* 0..127 */
            int e = (g & 3) << 3;          /* 0,8,16,24 halves */
            cp16(sB[st] + (unsigned)(r * HPITCH + e) * 2,
                 BT + (size_t)(col0 + r) * K + kt + e, true);
        }
    };
    auto issueAh = [&](int kt, int st) {
        #pragma unroll
        for (int i = 0; i < 2; i++) {
            int g = tid + i * 256;
            int r = g >> 2;
            int e = (g & 3) << 3;
            cp16(sA[st] + (unsigned)(r * HPITCH + e) * 2,
                 Ah + (size_t)(row0 + r) * K + kt + e, row0 + r < M);
        }
    };
    auto ldgA = [&](int kt) {
        #pragma unroll
        for (int i = 0; i < 4; i++) {
            int g = tid + i * 256;         /* 0..1023 */
            int r = g >> 3;                /* 0..127  */
            int e = (g & 7) << 2;          /* 0..28 floats */
            va[i] = make_float4(0.f, 0.f, 0.f, 0.f); wa[i] = va[i];
            if (row0 + r < M) {
                va[i] = *(const float4*)(Af + (size_t)(row0 + r) * K + kt + e);
                wa[i] = *(const float4*)(A2 + (size_t)(row0 + r) * K + kt + e);
            }
        }
    };
    auto stsA = [&](int st) {
        #pragma unroll
        for (int i = 0; i < 4; i++) {
            int g = tid + i * 256;
            int r = g >> 3;
            int e = (g & 7) << 2;
            __half2 p0 = __floats2half2_rn(fmaf(alpha, va[i].x, wa[i].x),
                                           fmaf(alpha, va[i].y, wa[i].y));
            __half2 p1 = __floats2half2_rn(fmaf(alpha, va[i].z, wa[i].z),
                                           fmaf(alpha, va[i].w, wa[i].w));
            __half* d = &As[st][r * HPITCH + e];
            *(__half2*)(d)     = p0;
            *(__half2*)(d + 2) = p1;
        }
    };

    /* prologue: fill stage 0 */
    if (fuse) ldgA(0); else issueAh(0, 0);
    issueB(0, 0);
    cp_commit_fn();
    if (fuse) stsA(0);
    cp_wait0_fn();
    __syncthreads();

    const int nt = K >> 5;
    int cur = 0;
    for (int t = 0; t < nt; t++) {
        const bool more = (t + 1) < nt;
        const int nxt = cur ^ 1;
        if (more) {
            if (fuse) ldgA((t + 1) << 5); else issueAh((t + 1) << 5, nxt);
            issueB((t + 1) << 5, nxt);
            cp_commit_fn();
        }
        const __half* as = As[cur];
        const __half* bs = Bs[cur];
        #pragma unroll
        for (int ks = 0; ks < 2; ks++) {
            const int ko = ks * 16;
            uint32_t af[4][4];
            #pragma unroll
            for (int mi = 0; mi < 4; mi++) {
                int base = (wm + mi * 16 + qr) * HPITCH + ko + 2 * qc;
                af[mi][0] = *(const uint32_t*)(as + base);
                af[mi][1] = *(const uint32_t*)(as + base + 8 * HPITCH);
                af[mi][2] = *(const uint32_t*)(as + base + 8);
                af[mi][3] = *(const uint32_t*)(as + base + 8 * HPITCH + 8);
            }
            uint32_t bf[4][2];
            #pragma unroll
            for (int ni = 0; ni < 4; ni++) {
                int nb = (wn + ni * 8 + qr) * HPITCH + ko + 2 * qc;
                bf[ni][0] = *(const uint32_t*)(bs + nb);
                bf[ni][1] = *(const uint32_t*)(bs + nb + 8);
            }
            #pragma unroll
            for (int mi = 0; mi < 4; mi++)
                #pragma unroll
                for (int ni = 0; ni < 4; ni++) {
                    asm volatile(
                        "mma.sync.aligned.m16n8k16.row.col.f32.f16.f16.f32 "
                        "{%0,%1,%2,%3}, {%4,%5,%6,%7}, {%8,%9}, {%0,%1,%2,%3};"
                        : "+f"(acc[mi][ni][0]), "+f"(acc[mi][ni][1]),
                          "+f"(acc[mi][ni][2]), "+f"(acc[mi][ni][3])
                        : "r"(af[mi][0]), "r"(af[mi][1]),
                          "r"(af[mi][2]), "r"(af[mi][3]),
                          "r"(bf[ni][0]), "r"(bf[ni][1]));
                }
        }
        if (more) {
            if (fuse) stsA(nxt);
            cp_wait0_fn();
            __syncthreads();
            cur = nxt;
        }
    }

    /* epilogue: c0:(r,c) c1:(r,c+1) c2:(r+8,c) c3:(r+8,c+1), no bias */
    #pragma unroll
    for (int mi = 0; mi < 4; mi++) {
        int r0 = row0 + wm + mi * 16 + qr;
        int r1 = r0 + 8;
        #pragma unroll
        for (int ni = 0; ni < 4; ni++) {
            int cc = col0 + wn + ni * 8 + qc * 2;
            if (r0 < M) {
                float2 o = make_float2(acc[mi][ni][0], acc[mi][ni][1]);
                *(float2*)(C + (size_t)r0 * Nn + cc) = o;
            }
            if (r1 < M) {
                float2 o = make_float2(acc[mi][ni][2], acc[mi][ni][3]);
                *(float2*)(C + (size_t)r1 * Nn + cc) = o;
            }
        }
    }
}

/* row LayerNorm(in + bias) + exact gelu; OUTPUT IS HALF (feeds GEMM A) */
__global__ void ln_act_kernel(const float* __restrict__ in,
                              const float* __restrict__ bias,
                              const float* __restrict__ gw,
                              const float* __restrict__ bw,
                              __half* __restrict__ out, int W, int do_gelu) {
    size_t row = blockIdx.x;
    int j = threadIdx.x * 4;
    bool act = j < W;
    float4 v = make_float4(0.f, 0.f, 0.f, 0.f);
    if (act) {
        v = *(const float4*)(in + row * W + j);
        float4 bb = *(const float4*)(bias + j);
        v.x += bb.x; v.y += bb.y; v.z += bb.z; v.w += bb.w;
    }
    float s = v.x + v.y + v.z + v.w;
    float ss = v.x * v.x + v.y * v.y + v.z * v.z + v.w * v.w;
    block_reduce2(s, ss);
    float m = s / (float)W;
    float rstd = rsqrtf(ss / (float)W - m * m + 1e-5f);
    if (act) {
        float4 g = *(const float4*)(gw + j);
        float4 b = *(const float4*)(bw + j);
        float4 ov;
        ov.x = (v.x - m) * rstd * g.x + b.x;
        ov.y = (v.y - m) * rstd * g.y + b.y;
        ov.z = (v.z - m) * rstd * g.z + b.z;
        ov.w = (v.w - m) * rstd * g.w + b.w;
        if (do_gelu) {
            ov.x = gelu_f(ov.x); ov.y = gelu_f(ov.y);
            ov.z = gelu_f(ov.z); ov.w = gelu_f(ov.w);
        }
        __half2 p0 = __floats2half2_rn(ov.x, ov.y);
        __half2 p1 = __floats2half2_rn(ov.z, ov.w);
        *(__half2*)(out + row * W + j)     = p0;
        *(__half2*)(out + row * W + j + 2) = p1;
    }
}

/* h_new = gelu?(LN(t2 + bias)) + h_old [+ vn_next[batch]]; optional aggr=0 */
__global__ void ln_res_fused_kernel(const float* __restrict__ t2,
                                    const float* __restrict__ bias,
                                    const float* __restrict__ gw,
                                    const float* __restrict__ bw,
                                    const float* __restrict__ vn,
                                    const int* __restrict__ batch,
                                    float* __restrict__ h,
                                    float* __restrict__ aggr,
                                    int do_gelu) {
    size_t row = blockIdx.x;
    int j = threadIdx.x;
    size_t idx = row * HH + j;
    float v = t2[idx] + bias[j];
    float s = v, ss = v * v;
    block_reduce2(s, ss);
    float m = s * (1.f / HH);
    float rstd = rsqrtf(ss * (1.f / HH) - m * m + 1e-5f);
    float ov = (v - m) * rstd * gw[j] + bw[j];
    if (do_gelu) ov = gelu_f(ov);
    ov += h[idx];
    if (vn) {
        int g = batch[row];
        ov += vn[(size_t)g * HH + j];
        aggr[idx] = 0.f;
    }
    h[idx] = ov;
}

__global__ void segmax_kernel(const float* __restrict__ hin,
                              __half* __restrict__ vp) {
    int idx = blockIdx.x * 256 + threadIdx.x;
    int g = idx >> 8;
    int j = idx & (HH - 1);
    const float* base = hin + (size_t)g * NP * HH + j;
    float m = base[0];
    #pragma unroll
    for (int t = 1; t < NP; t++) m = fmaxf(m, base[(size_t)t * HH]);
    vp[idx] = __float2half_rn(m);
}

__global__ void segsum_kernel(const float* __restrict__ h,
                              __half* __restrict__ o) {
    int idx = blockIdx.x * 256 + threadIdx.x;
    int g = idx >> 8;
    int j = idx & (HH - 1);
    const float* base = h + (size_t)g * NP * HH + j;
    float s = 0.f;
    #pragma unroll
    for (int t = 0; t < NP; t++) s += base[(size_t)t * HH];
    o[idx] = __float2half_rn(s);
}

/* vn += t + bias (bias indexed by column) */
__global__ void vnadd_kernel(float* __restrict__ vn, const float* __restrict__ t,
                             const float* __restrict__ bias) {
    int idx = blockIdx.x * 256 + threadIdx.x;
    vn[idx] += t[idx] + bias[idx & (HH - 1)];
}

/* out = (z + bias) / ||z + bias||  row-wise, in place on z */
__global__ void l2norm_kernel(float* __restrict__ z, const float* __restrict__ bias) {
    size_t row = blockIdx.x;
    int j = threadIdx.x;
    float v = z[row * HH + j] + bias[j];
    float s = v * v, dummy = 0.f;
    block_reduce2(s, dummy);
    z[row * HH + j] = v * rsqrtf(s);
}

/* ---------------- host orchestration ---------------------------------------- */
extern "C" void kernel_launch(void* const* d_in, const int* in_sizes, int n_in,
                              void* d_out, int out_size) {
    const int*   x        = (const int*)  d_in[0];
    const int*   eidx     = (const int*)  d_in[1];
    const int*   eattr    = (const int*)  d_in[2];
    const int*   batch    = (const int*)  d_in[3];
    const float* atom_emb = (const float*)d_in[4];
    const float* vn_emb   = (const float*)d_in[5];
    const float* bond_emb = (const float*)d_in[6];
    const float* epsv     = (const float*)d_in[7];
    const float* c_w1  = (const float*)d_in[8];
    const float* c_b1  = (const float*)d_in[9];
    const float* c_lng = (const float*)d_in[10];
    const float* c_lnb = (const float*)d_in[11];
    const float* c_w2  = (const float*)d_in[12];
    const float* c_b2  = (const float*)d_in[13];
    const float* n_g   = (const float*)d_in[14];
    const float* n_b   = (const float*)d_in[15];
    const float* v_w1  = (const float*)d_in[16];
    const float* v_b1  = (const float*)d_in[17];
    const float* v_lng = (const float*)d_in[18];
    const float* v_lnb = (const float*)d_in[19];
    const float* v_w2  = (const float*)d_in[20];
    const float* v_b2  = (const float*)d_in[21];
    const float* p_w1  = (const float*)d_in[22];
    const float* p_b1  = (const float*)d_in[23];
    const float* p_lng = (const float*)d_in[24];
    const float* p_lnb = (const float*)d_in[25];
    const float* p_w2  = (const float*)d_in[26];
    const float* p_b2  = (const float*)d_in[27];
    float* outbuf = (float*)d_out;

    float  *hbuf, *aggrbuf, *obuf, *hidbuf, *vnbuf, *ghbuf, *tbuf;
    __half *hidh, *vph, *ghh, *th, *wtbuf;
    cudaGetSymbolAddress((void**)&hbuf,    g_h);
    cudaGetSymbolAddress((void**)&aggrbuf, g_aggr);
    cudaGetSymbolAddress((void**)&obuf,    g_o);
    cudaGetSymbolAddress((void**)&hidbuf,  g_hid);
    cudaGetSymbolAddress((void**)&hidh,    g_hidh);
    cudaGetSymbolAddress((void**)&vnbuf,   g_vn);
    cudaGetSymbolAddress((void**)&vph,     g_vph);
    cudaGetSymbolAddress((void**)&ghbuf,   g_gh);
    cudaGetSymbolAddress((void**)&ghh,     g_ghh);
    cudaGetSymbolAddress((void**)&tbuf,    g_t);
    cudaGetSymbolAddress((void**)&th,      g_th);
    cudaGetSymbolAddress((void**)&wtbuf,   g_wt);

    __half* cw1t = wtbuf + OFF_CW1;
    __half* cw2t = wtbuf + OFF_CW2;
    __half* vw1t = wtbuf + OFF_VW1;
    __half* vw2t = wtbuf + OFF_VW2;
    __half* pw1t = wtbuf + OFF_PW1;
    __half* pw2t = wtbuf + OFF_PW2;

    const int* src = eidx;
    const int* dst = eidx + EE;

    const int nodeBlocks = NN * 64 / 256;
    const int edgeBlocks = EE * 64 / 256;
    const int gBlocks    = GG * HH / 256;
    const dim3 gemmN1(H4 / 128, (NN + 127) / 128);
    const dim3 gemmN2(HH / 128, (NN + 127) / 128);
    const dim3 gemmG1(H4 / 128, (GG + 127) / 128);
    const dim3 gemmG2(HH / 128, (GG + 127) / 128);
    const dim3 tb(32, 8);

    transpose_w_kernel<<<dim3(H4 / 32, HH / 32, LL),     tb>>>(c_w1, cw1t, HH, H4);
    transpose_w_kernel<<<dim3(HH / 32, H4 / 32, LL),     tb>>>(c_w2, cw2t, H4, HH);
    transpose_w_kernel<<<dim3(H4 / 32, HH / 32, LL - 1), tb>>>(v_w1, vw1t, HH, H4);
    transpose_w_kernel<<<dim3(HH / 32, H4 / 32, LL - 1), tb>>>(v_w2, vw2t, H4, HH);
    transpose_w_kernel<<<dim3(HH / 32, HH / 32, 1),      tb>>>(p_w1, pw1t, HH, HH);
    transpose_w_kernel<<<dim3(HH / 32, HH / 32, 1),      tb>>>(p_w2, pw2t, HH, HH);

    init_h_kernel<<<nodeBlocks, 256>>>(x, atom_emb, hbuf);
    init_vn_kernel<<<gBlocks, 256>>>(vn_emb, vnbuf);
    addvn_kernel<<<nodeBlocks, 256>>>(vnbuf, batch, hbuf, aggrbuf);

    for (int l = 0; l < LL; l++) {
        edge_kernel<<<edgeBlocks, 256>>>(src, dst, eattr,
                                         bond_emb + (size_t)l * 5 * HH, hbuf, aggrbuf);
        /* GEMM1: hid = ((1+eps)*h + aggr) @ c_w1 (fp16 fused-A path) */
        gemm16<<<gemmN1, 256>>>(hbuf, aggrbuf, (const __half*)nullptr, epsv, l,
                                cw1t + (size_t)l * HH * H4,
                                hidbuf, NN, H4, HH, 1);
        ln_act_kernel<<<NN, 256>>>(hidbuf, c_b1 + (size_t)l * H4,
                                   c_lng + (size_t)l * H4,
                                   c_lnb + (size_t)l * H4, hidh, H4, 1);
        /* GEMM2: o = hid_h @ c_w2 */
        gemm16<<<gemmN2, 256>>>(nullptr, nullptr, hidh, nullptr, 0,
                                cw2t + (size_t)l * H4 * HH,
                                obuf, NN, HH, H4, 0);
        if (l < LL - 1) {
            segmax_kernel<<<gBlocks, 256>>>(hbuf, vph);
            gemm16<<<gemmG1, 256>>>(nullptr, nullptr, vph, nullptr, 0,
                                    vw1t + (size_t)l * HH * H4,
                                    ghbuf, GG, H4, HH, 0);
            ln_act_kernel<<<GG, 256>>>(ghbuf, v_b1 + (size_t)l * H4,
                                       v_lng + (size_t)l * H4,
                                       v_lnb + (size_t)l * H4, ghh, H4, 1);
            gemm16<<<gemmG2, 256>>>(nullptr, nullptr, ghh, nullptr, 0,
                                    vw2t + (size_t)l * H4 * HH,
                                    tbuf, GG, HH, H4, 0);
            vnadd_kernel<<<gBlocks, 256>>>(vnbuf, tbuf, v_b2 + (size_t)l * HH);
            ln_res_fused_kernel<<<NN, 256>>>(obuf, c_b2 + (size_t)l * HH,
                                             n_g + (size_t)l * HH,
                                             n_b + (size_t)l * HH,
                                             vnbuf, batch, hbuf, aggrbuf, 1);
        } else {
            ln_res_fused_kernel<<<NN, 256>>>(obuf, c_b2 + (size_t)l * HH,
                                             n_g + (size_t)l * HH,
                                             n_b + (size_t)l * HH,
                                             nullptr, batch, hbuf, aggrbuf, 0);
        }
    }

    segsum_kernel<<<gBlocks, 256>>>(hbuf, vph);
    gemm16<<<gemmG2, 256>>>(nullptr, nullptr, vph, nullptr, 0,
                            pw1t, tbuf, GG, HH, HH, 0);
    ln_act_kernel<<<GG, 256>>>(tbuf, p_b1, p_lng, p_lnb, th, HH, 1);
    gemm16<<<gemmG2, 256>>>(nullptr, nullptr, th, nullptr, 0,
                            pw2t, outbuf, GG, HH, HH, 0);
    l2norm_kernel<<<GG, 256>>>(outbuf, p_b2);
}

// round 17
// speedup vs baseline: 3.8312x; 1.0601x over previous
#include <cuda_runtime.h>
#include <cuda_bf16.h>
#include <cuda_fp16.h>
#include <cstdint>
#include <math.h>

#define NN 200000
#define EE 400000
#define GG 8000
#define HH 256
#define H4 1024
#define LL 5
#define NP 25   /* nodes per graph = NN/GG */

/* ---------------- scratch (device globals; no allocations allowed) --------- */
__device__ float  g_h   [(size_t)NN * HH];
__device__ float  g_aggr[(size_t)NN * HH];
__device__ float  g_o   [(size_t)NN * HH];
__device__ __half g_hidr[(size_t)NN * H4];   /* GEMM1 raw output (half)  */
__device__ __half g_hidh[(size_t)NN * H4];   /* ln_act output (half)     */
__device__ float  g_vn  [(size_t)GG * HH];
__device__ __half g_vph [(size_t)GG * HH];
__device__ __half g_ghr [(size_t)GG * H4];
__device__ __half g_ghh [(size_t)GG * H4];
__device__ float  g_t   [(size_t)GG * HH];
__device__ __half g_tr  [(size_t)GG * HH];
__device__ __half g_th  [(size_t)GG * HH];

/* half, TRANSPOSED weights ([N][K] layout) */
#define OFF_CW1 0
#define OFF_CW2 (OFF_CW1 + LL * HH * H4)
#define OFF_VW1 (OFF_CW2 + LL * H4 * HH)
#define OFF_VW2 (OFF_VW1 + (LL - 1) * HH * H4)
#define OFF_PW1 (OFF_VW2 + (LL - 1) * H4 * HH)
#define OFF_PW2 (OFF_PW1 + HH * HH)
#define WT_TOTAL (OFF_PW2 + HH * HH)
__device__ __half g_wt[WT_TOTAL];

/* ---------------- helpers --------------------------------------------------- */
__device__ __forceinline__ float gelu_f(float x) {
    return 0.5f * x * (1.0f + erff(x * 0.70710678118654752f));
}

__device__ __forceinline__ void cp16(unsigned d, const void* s, bool pred) {
    asm volatile("cp.async.cg.shared.global [%0], [%1], 16, %2;"
                 :: "r"(d), "l"(s), "r"(pred ? 16u : 0u));
}
__device__ __forceinline__ void cp_commit_fn() {
    asm volatile("cp.async.commit_group;");
}
__device__ __forceinline__ void cp_wait1_fn() {
    asm volatile("cp.async.wait_group 1;");
}

__device__ __forceinline__ void block_reduce2(float& s, float& ss) {
    __shared__ float r1[8], r2[8], fin[2];
    #pragma unroll
    for (int o = 16; o > 0; o >>= 1) {
        s  += __shfl_down_sync(0xffffffffu, s,  o);
        ss += __shfl_down_sync(0xffffffffu, ss, o);
    }
    int w = threadIdx.x >> 5, l = threadIdx.x & 31;
    if (l == 0) { r1[w] = s; r2[w] = ss; }
    __syncthreads();
    if (threadIdx.x < 32) {
        float a = (threadIdx.x < 8) ? r1[threadIdx.x] : 0.f;
        float b = (threadIdx.x < 8) ? r2[threadIdx.x] : 0.f;
        #pragma unroll
        for (int o = 4; o > 0; o >>= 1) {
            a += __shfl_down_sync(0xffffffffu, a, o);
            b += __shfl_down_sync(0xffffffffu, b, o);
        }
        if (threadIdx.x == 0) { fin[0] = a; fin[1] = b; }
    }
    __syncthreads();
    s = fin[0]; ss = fin[1];
}

/* ---------------- weight prep: transpose + half convert --------------------- */
__global__ void transpose_w_kernel(const float* __restrict__ src,
                                   __half* __restrict__ dst, int K, int N) {
    __shared__ float tile[32][33];
    size_t boff = (size_t)blockIdx.z * K * N;
    int k0 = blockIdx.y * 32, n0 = blockIdx.x * 32;
    #pragma unroll
    for (int i = threadIdx.y; i < 32; i += 8)
        tile[i][threadIdx.x] =
            src[boff + (size_t)(k0 + i) * N + n0 + threadIdx.x];
    __syncthreads();
    #pragma unroll
    for (int i = threadIdx.y; i < 32; i += 8)
        dst[boff + (size_t)(n0 + i) * K + k0 + threadIdx.x] =
            __float2half_rn(tile[threadIdx.x][i]);
}

/* ---------------- elementwise kernels --------------------------------------- */
__global__ void init_h_kernel(const int* __restrict__ x,
                              const float* __restrict__ emb,
                              float* __restrict__ h) {
    size_t idx = (size_t)blockIdx.x * 256 + threadIdx.x;
    int i = (int)(idx >> 6);
    int c = (int)(idx & 63) << 2;
    int a = x[i];
    *(float4*)(h + (size_t)i * HH + c) = *(const float4*)(emb + (size_t)a * HH + c);
}

__global__ void init_vn_kernel(const float* __restrict__ vn_emb,
                               float* __restrict__ vn) {
    int idx = blockIdx.x * 256 + threadIdx.x;
    vn[idx] = vn_emb[idx & (HH - 1)];
}

__global__ void addvn_kernel(const float* __restrict__ vn,
                             const int* __restrict__ batch,
                             float* __restrict__ h,
                             float* __restrict__ aggr) {
    size_t idx = (size_t)blockIdx.x * 256 + threadIdx.x;
    int i = (int)(idx >> 6);
    int c = (int)(idx & 63) << 2;
    int g = batch[i];
    float4 hv = *(float4*)(h + (size_t)i * HH + c);
    float4 vv = *(const float4*)(vn + (size_t)g * HH + c);
    hv.x += vv.x; hv.y += vv.y; hv.z += vv.z; hv.w += vv.w;
    *(float4*)(h    + (size_t)i * HH + c) = hv;
    *(float4*)(aggr + (size_t)i * HH + c) = make_float4(0.f, 0.f, 0.f, 0.f);
}

__global__ void edge_kernel(const int* __restrict__ src,
                            const int* __restrict__ dst,
                            const int* __restrict__ attr,
                            const float* __restrict__ bond,
                            const float* __restrict__ h,
                            float* __restrict__ aggr) {
    size_t idx = (size_t)blockIdx.x * 256 + threadIdx.x;
    int e = (int)(idx >> 6);
    int c = (int)(idx & 63) << 2;
    int s = __ldg(src + e), d = __ldg(dst + e), a = __ldg(attr + e);
    float4 hv = *(const float4*)(h + (size_t)s * HH + c);
    float4 bv = *(const float4*)(bond + (size_t)a * HH + c);
    float4 m;
    m.x = gelu_f(hv.x + bv.x);
    m.y = gelu_f(hv.y + bv.y);
    m.z = gelu_f(hv.z + bv.z);
    m.w = gelu_f(hv.w + bv.w);
    float* p = aggr + (size_t)d * HH + c;
    atomicAdd(p + 0, m.x);
    atomicAdd(p + 1, m.y);
    atomicAdd(p + 2, m.z);
    atomicAdd(p + 3, m.w);
}

/* ---------------- fp16 mma.sync GEMM ------------------------------------------
   C = A_eff[M,K] @ BT[Nn,K]^T  (no bias). fuse: A from float pair; else half A.
   halfout: write half to Ch, else float to Cf.
   Block 128x128, BK=32, 3 stages (dyn smem), 8 warps 64x32, m16n8k16,
   ldmatrix fragment loads, smem pitch 40 halves (conflict-free). */
#define HPITCH 40
#define HSZ (128 * HPITCH)                 /* halves per stage buffer */
#define STG_BYTES (HSZ * 2)                /* 10240 bytes */
#define GSM_BYTES (6 * STG_BYTES)          /* 3 stages x (A+B) = 61440 */

__global__ void __launch_bounds__(256)
gemm16(const float* __restrict__ Af, const float* __restrict__ A2,
       const __half* __restrict__ Ah,
       const float* __restrict__ epsp, int epsi,
       const __half* __restrict__ BT,
       float* __restrict__ Cf, __half* __restrict__ Ch,
       int M, int Nn, int K, int fuse, int halfout) {
    extern __shared__ __half smh[];
    const int tid  = threadIdx.x;
    const int lane = tid & 31;
    const int warp = tid >> 5;
    const int wm   = (warp >> 2) * 64;
    const int wn   = (warp & 3) * 32;
    const int qr   = lane >> 2;
    const int qc   = lane & 3;

    const int row0 = blockIdx.y * 128;
    const int col0 = blockIdx.x * 128;

    float alpha = 1.0f;
    if (fuse) alpha = 1.0f + __ldg(&epsp[epsi]);

    const uint32_t smb = (uint32_t)__cvta_generic_to_shared(smh);
    /* stage s: A at smb + s*STG_BYTES, B at smb + (3+s)*STG_BYTES */

    /* ldmatrix lane address components */
    const int arow = (lane & 7) + ((lane >> 3) & 1) * 8;
    const int acol = (lane >> 4) * 8;
    const int brow = lane & 7;
    const int bcol = ((lane >> 3) & 1) * 8;

    float acc[4][4][4];
    #pragma unroll
    for (int mi = 0; mi < 4; mi++)
        #pragma unroll
        for (int ni = 0; ni < 4; ni++)
            #pragma unroll
            for (int r = 0; r < 4; r++) acc[mi][ni][r] = 0.f;

    float4 va[4], wa[4];

    auto fill = [&](int kt, int s) {
        if (fuse) {
            #pragma unroll
            for (int i = 0; i < 4; i++) {
                int g = tid + i * 256;
                int r = g >> 3;
                int e = (g & 7) << 2;
                va[i] = make_float4(0.f, 0.f, 0.f, 0.f); wa[i] = va[i];
                if (row0 + r < M) {
                    va[i] = *(const float4*)(Af + (size_t)(row0 + r) * K + kt + e);
                    wa[i] = *(const float4*)(A2 + (size_t)(row0 + r) * K + kt + e);
                }
            }
            #pragma unroll
            for (int i = 0; i < 4; i++) {
                int g = tid + i * 256;
                int r = g >> 3;
                int e = (g & 7) << 2;
                __half2 p0 = __floats2half2_rn(fmaf(alpha, va[i].x, wa[i].x),
                                               fmaf(alpha, va[i].y, wa[i].y));
                __half2 p1 = __floats2half2_rn(fmaf(alpha, va[i].z, wa[i].z),
                                               fmaf(alpha, va[i].w, wa[i].w));
                __half* d = smh + s * HSZ + r * HPITCH + e;
                *(__half2*)(d)     = p0;
                *(__half2*)(d + 2) = p1;
            }
        } else {
            #pragma unroll
            for (int i = 0; i < 2; i++) {
                int g = tid + i * 256;
                int r = g >> 2;
                int e = (g & 3) << 3;
                cp16(smb + s * STG_BYTES + (unsigned)(r * HPITCH + e) * 2,
                     Ah + (size_t)(row0 + r) * K + kt + e, row0 + r < M);
            }
        }
        #pragma unroll
        for (int i = 0; i < 2; i++) {
            int g = tid + i * 256;
            int r = g >> 2;
            int e = (g & 3) << 3;
            cp16(smb + (3 + s) * STG_BYTES + (unsigned)(r * HPITCH + e) * 2,
                 BT + (size_t)(col0 + r) * K + kt + e, true);
        }
    };

    const int nt = K >> 5;
    fill(0, 0);
    cp_commit_fn();
    if (nt > 1) fill(32, 1);
    cp_commit_fn();
    cp_wait1_fn();
    __syncthreads();

    for (int t = 0; t < nt; t++) {
        const int cur = t % 3;
        const uint32_t aB = smb + cur * STG_BYTES;
        const uint32_t bB = smb + (3 + cur) * STG_BYTES;
        #pragma unroll
        for (int ks = 0; ks < 2; ks++) {
            const int ko = ks * 16;
            uint32_t af[4][4];
            #pragma unroll
            for (int mi = 0; mi < 4; mi++) {
                uint32_t aaddr = aB +
                    (uint32_t)(((wm + mi * 16 + arow) * HPITCH + ko + acol) * 2);
                asm volatile(
                    "ldmatrix.sync.aligned.m8n8.x4.shared.b16 "
                    "{%0, %1, %2, %3}, [%4];"
                    : "=r"(af[mi][0]), "=r"(af[mi][1]),
                      "=r"(af[mi][2]), "=r"(af[mi][3])
                    : "r"(aaddr));
            }
            uint32_t bf[4][2];
            #pragma unroll
            for (int ni = 0; ni < 4; ni++) {
                uint32_t baddr = bB +
                    (uint32_t)(((wn + ni * 8 + brow) * HPITCH + ko + bcol) * 2);
                asm volatile(
                    "ldmatrix.sync.aligned.m8n8.x2.shared.b16 "
                    "{%0, %1}, [%2];"
                    : "=r"(bf[ni][0]), "=r"(bf[ni][1])
                    : "r"(baddr));
            }
            #pragma unroll
            for (int mi = 0; mi < 4; mi++)
                #pragma unroll
                for (int ni = 0; ni < 4; ni++) {
                    asm volatile(
                        "mma.sync.aligned.m16n8k16.row.col.f32.f16.f16.f32 "
                        "{%0,%1,%2,%3}, {%4,%5,%6,%7}, {%8,%9}, {%0,%1,%2,%3};"
                        : "+f"(acc[mi][ni][0]), "+f"(acc[mi][ni][1]),
                          "+f"(acc[mi][ni][2]), "+f"(acc[mi][ni][3])
                        : "r"(af[mi][0]), "r"(af[mi][1]),
                          "r"(af[mi][2]), "r"(af[mi][3]),
                          "r"(bf[ni][0]), "r"(bf[ni][1]));
                }
        }
        int u = t + 2;
        if (u < nt) fill(u << 5, u % 3);
        cp_commit_fn();
        cp_wait1_fn();
        __syncthreads();
    }

    /* epilogue: c0:(r,c) c1:(r,c+1) c2:(r+8,c) c3:(r+8,c+1) */
    #pragma unroll
    for (int mi = 0; mi < 4; mi++) {
        int r0 = row0 + wm + mi * 16 + qr;
        int r1 = r0 + 8;
        #pragma unroll
        for (int ni = 0; ni < 4; ni++) {
            int cc = col0 + wn + ni * 8 + qc * 2;
            if (halfout) {
                if (r0 < M)
                    *(__half2*)(Ch + (size_t)r0 * Nn + cc) =
                        __floats2half2_rn(acc[mi][ni][0], acc[mi][ni][1]);
                if (r1 < M)
                    *(__half2*)(Ch + (size_t)r1 * Nn + cc) =
                        __floats2half2_rn(acc[mi][ni][2], acc[mi][ni][3]);
            } else {
                if (r0 < M)
                    *(float2*)(Cf + (size_t)r0 * Nn + cc) =
                        make_float2(acc[mi][ni][0], acc[mi][ni][1]);
                if (r1 < M)
                    *(float2*)(Cf + (size_t)r1 * Nn + cc) =
                        make_float2(acc[mi][ni][2], acc[mi][ni][3]);
            }
        }
    }
}

/* row LayerNorm(in_half + bias) + exact gelu; output half (feeds GEMM A) */
__global__ void ln_act_kernel(const __half* __restrict__ in,
                              const float* __restrict__ bias,
                              const float* __restrict__ gw,
                              const float* __restrict__ bw,
                              __half* __restrict__ out, int W, int do_gelu) {
    size_t row = blockIdx.x;
    int j = threadIdx.x * 4;
    bool act = j < W;
    float4 v = make_float4(0.f, 0.f, 0.f, 0.f);
    if (act) {
        __half2 h0 = *(const __half2*)(in + row * W + j);
        __half2 h1 = *(const __half2*)(in + row * W + j + 2);
        float2 f0 = __half22float2(h0);
        float2 f1 = __half22float2(h1);
        float4 bb = *(const float4*)(bias + j);
        v.x = f0.x + bb.x; v.y = f0.y + bb.y;
        v.z = f1.x + bb.z; v.w = f1.y + bb.w;
    }
    float s = v.x + v.y + v.z + v.w;
    float ss = v.x * v.x + v.y * v.y + v.z * v.z + v.w * v.w;
    block_reduce2(s, ss);
    float m = s / (float)W;
    float rstd = rsqrtf(ss / (float)W - m * m + 1e-5f);
    if (act) {
        float4 g = *(const float4*)(gw + j);
        float4 b = *(const float4*)(bw + j);
        float4 ov;
        ov.x = (v.x - m) * rstd * g.x + b.x;
        ov.y = (v.y - m) * rstd * g.y + b.y;
        ov.z = (v.z - m) * rstd * g.z + b.z;
        ov.w = (v.w - m) * rstd * g.w + b.w;
        if (do_gelu) {
            ov.x = gelu_f(ov.x); ov.y = gelu_f(ov.y);
            ov.z = gelu_f(ov.z); ov.w = gelu_f(ov.w);
        }
        *(__half2*)(out + row * W + j)     = __floats2half2_rn(ov.x, ov.y);
        *(__half2*)(out + row * W + j + 2) = __floats2half2_rn(ov.z, ov.w);
    }
}

/* h_new = gelu?(LN(t2 + bias)) + h_old [+ vn_next[batch]]; optional aggr=0 */
__global__ void ln_res_fused_kernel(const float* __restrict__ t2,
                                    const float* __restrict__ bias,
                                    const float* __restrict__ gw,
                                    const float* __restrict__ bw,
                                    const float* __restrict__ vn,
                                    const int* __restrict__ batch,
                                    float* __restrict__ h,
                                    float* __restrict__ aggr,
                                    int do_gelu) {
    size_t row = blockIdx.x;
    int j = threadIdx.x;
    size_t idx = row * HH + j;
    float v = t2[idx] + bias[j];
    float s = v, ss = v * v;
    block_reduce2(s, ss);
    float m = s * (1.f / HH);
    float rstd = rsqrtf(ss * (1.f / HH) - m * m + 1e-5f);
    float ov = (v - m) * rstd * gw[j] + bw[j];
    if (do_gelu) ov = gelu_f(ov);
    ov += h[idx];
    if (vn) {
        int g = batch[row];
        ov += vn[(size_t)g * HH + j];
        aggr[idx] = 0.f;
    }
    h[idx] = ov;
}

__global__ void segmax_kernel(const float* __restrict__ hin,
                              __half* __restrict__ vp) {
    int idx = blockIdx.x * 256 + threadIdx.x;
    int g = idx >> 8;
    int j = idx & (HH - 1);
    const float* base = hin + (size_t)g * NP * HH + j;
    float m = base[0];
    #pragma unroll
    for (int t = 1; t < NP; t++) m = fmaxf(m, base[(size_t)t * HH]);
    vp[idx] = __float2half_rn(m);
}

__global__ void segsum_kernel(const float* __restrict__ h,
                              __half* __restrict__ o) {
    int idx = blockIdx.x * 256 + threadIdx.x;
    int g = idx >> 8;
    int j = idx & (HH - 1);
    const float* base = h + (size_t)g * NP * HH + j;
    float s = 0.f;
    #pragma unroll
    for (int t = 0; t < NP; t++) s += base[(size_t)t * HH];
    o[idx] = __float2half_rn(s);
}

__global__ void vnadd_kernel(float* __restrict__ vn, const float* __restrict__ t,
                             const float* __restrict__ bias) {
    int idx = blockIdx.x * 256 + threadIdx.x;
    vn[idx] += t[idx] + bias[idx & (HH - 1)];
}

__global__ void l2norm_kernel(float* __restrict__ z, const float* __restrict__ bias) {
    size_t row = blockIdx.x;
    int j = threadIdx.x;
    float v = z[row * HH + j] + bias[j];
    float s = v * v, dummy = 0.f;
    block_reduce2(s, dummy);
    z[row * HH + j] = v * rsqrtf(s);
}

/* ---------------- host orchestration ---------------------------------------- */
extern "C" void kernel_launch(void* const* d_in, const int* in_sizes, int n_in,
                              void* d_out, int out_size) {
    const int*   x        = (const int*)  d_in[0];
    const int*   eidx     = (const int*)  d_in[1];
    const int*   eattr    = (const int*)  d_in[2];
    const int*   batch    = (const int*)  d_in[3];
    const float* atom_emb = (const float*)d_in[4];
    const float* vn_emb   = (const float*)d_in[5];
    const float* bond_emb = (const float*)d_in[6];
    const float* epsv     = (const float*)d_in[7];
    const float* c_w1  = (const float*)d_in[8];
    const float* c_b1  = (const float*)d_in[9];
    const float* c_lng = (const float*)d_in[10];
    const float* c_lnb = (const float*)d_in[11];
    const float* c_w2  = (const float*)d_in[12];
    const float* c_b2  = (const float*)d_in[13];
    const float* n_g   = (const float*)d_in[14];
    const float* n_b   = (const float*)d_in[15];
    const float* v_w1  = (const float*)d_in[16];
    const float* v_b1  = (const float*)d_in[17];
    const float* v_lng = (const float*)d_in[18];
    const float* v_lnb = (const float*)d_in[19];
    const float* v_w2  = (const float*)d_in[20];
    const float* v_b2  = (const float*)d_in[21];
    const float* p_w1  = (const float*)d_in[22];
    const float* p_b1  = (const float*)d_in[23];
    const float* p_lng = (const float*)d_in[24];
    const float* p_lnb = (const float*)d_in[25];
    const float* p_w2  = (const float*)d_in[26];
    const float* p_b2  = (const float*)d_in[27];
    float* outbuf = (float*)d_out;

    float  *hbuf, *aggrbuf, *obuf, *vnbuf, *tbuf;
    __half *hidr, *hidh, *vph, *ghr, *ghh, *tr, *th, *wtbuf;
    cudaGetSymbolAddress((void**)&hbuf,    g_h);
    cudaGetSymbolAddress((void**)&aggrbuf, g_aggr);
    cudaGetSymbolAddress((void**)&obuf,    g_o);
    cudaGetSymbolAddress((void**)&hidr,    g_hidr);
    cudaGetSymbolAddress((void**)&hidh,    g_hidh);
    cudaGetSymbolAddress((void**)&vnbuf,   g_vn);
    cudaGetSymbolAddress((void**)&vph,     g_vph);
    cudaGetSymbolAddress((void**)&ghr,     g_ghr);
    cudaGetSymbolAddress((void**)&ghh,     g_ghh);
    cudaGetSymbolAddress((void**)&tbuf,    g_t);
    cudaGetSymbolAddress((void**)&tr,      g_tr);
    cudaGetSymbolAddress((void**)&th,      g_th);
    cudaGetSymbolAddress((void**)&wtbuf,   g_wt);

    __half* cw1t = wtbuf + OFF_CW1;
    __half* cw2t = wtbuf + OFF_CW2;
    __half* vw1t = wtbuf + OFF_VW1;
    __half* vw2t = wtbuf + OFF_VW2;
    __half* pw1t = wtbuf + OFF_PW1;
    __half* pw2t = wtbuf + OFF_PW2;

    cudaFuncSetAttribute(gemm16, cudaFuncAttributeMaxDynamicSharedMemorySize,
                         GSM_BYTES);

    const int* src = eidx;
    const int* dst = eidx + EE;

    const int nodeBlocks = NN * 64 / 256;
    const int edgeBlocks = EE * 64 / 256;
    const int gBlocks    = GG * HH / 256;
    const dim3 gemmN1(H4 / 128, (NN + 127) / 128);
    const dim3 gemmN2(HH / 128, (NN + 127) / 128);
    const dim3 gemmG1(H4 / 128, (GG + 127) / 128);
    const dim3 gemmG2(HH / 128, (GG + 127) / 128);
    const dim3 tb(32, 8);

    transpose_w_kernel<<<dim3(H4 / 32, HH / 32, LL),     tb>>>(c_w1, cw1t, HH, H4);
    transpose_w_kernel<<<dim3(HH / 32, H4 / 32, LL),     tb>>>(c_w2, cw2t, H4, HH);
    transpose_w_kernel<<<dim3(H4 / 32, HH / 32, LL - 1), tb>>>(v_w1, vw1t, HH, H4);
    transpose_w_kernel<<<dim3(HH / 32, H4 / 32, LL - 1), tb>>>(v_w2, vw2t, H4, HH);
    transpose_w_kernel<<<dim3(HH / 32, HH / 32, 1),      tb>>>(p_w1, pw1t, HH, HH);
    transpose_w_kernel<<<dim3(HH / 32, HH / 32, 1),      tb>>>(p_w2, pw2t, HH, HH);

    init_h_kernel<<<nodeBlocks, 256>>>(x, atom_emb, hbuf);
    init_vn_kernel<<<gBlocks, 256>>>(vn_emb, vnbuf);
    addvn_kernel<<<nodeBlocks, 256>>>(vnbuf, batch, hbuf, aggrbuf);

    for (int l = 0; l < LL; l++) {
        edge_kernel<<<edgeBlocks, 256>>>(src, dst, eattr,
                                         bond_emb + (size_t)l * 5 * HH, hbuf, aggrbuf);
        /* GEMM1: hid_half = ((1+eps)*h + aggr) @ c_w1 */
        gemm16<<<gemmN1, 256, GSM_BYTES>>>(hbuf, aggrbuf, (const __half*)nullptr,
                                           epsv, l, cw1t + (size_t)l * HH * H4,
                                           nullptr, hidr, NN, H4, HH, 1, 1);
        ln_act_kernel<<<NN, 256>>>(hidr, c_b1 + (size_t)l * H4,
                                   c_lng + (size_t)l * H4,
                                   c_lnb + (size_t)l * H4, hidh, H4, 1);
        /* GEMM2: o = hid_h @ c_w2 (float out) */
        gemm16<<<gemmN2, 256, GSM_BYTES>>>(nullptr, nullptr, hidh, nullptr, 0,
                                           cw2t + (size_t)l * H4 * HH,
                                           obuf, nullptr, NN, HH, H4, 0, 0);
        if (l < LL - 1) {
            segmax_kernel<<<gBlocks, 256>>>(hbuf, vph);
            gemm16<<<gemmG1, 256, GSM_BYTES>>>(nullptr, nullptr, vph, nullptr, 0,
                                               vw1t + (size_t)l * HH * H4,
                                               nullptr, ghr, GG, H4, HH, 0, 1);
            ln_act_kernel<<<GG, 256>>>(ghr, v_b1 + (size_t)l * H4,
                                       v_lng + (size_t)l * H4,
                                       v_lnb + (size_t)l * H4, ghh, H4, 1);
            gemm16<<<gemmG2, 256, GSM_BYTES>>>(nullptr, nullptr, ghh, nullptr, 0,
                                               vw2t + (size_t)l * H4 * HH,
                                               tbuf, nullptr, GG, HH, H4, 0, 0);
            vnadd_kernel<<<gBlocks, 256>>>(vnbuf, tbuf, v_b2 + (size_t)l * HH);
            ln_res_fused_kernel<<<NN, 256>>>(obuf, c_b2 + (size_t)l * HH,
                                             n_g + (size_t)l * HH,
                                             n_b + (size_t)l * HH,
                                             vnbuf, batch, hbuf, aggrbuf, 1);
        } else {
            ln_res_fused_kernel<<<NN, 256>>>(obuf, c_b2 + (size_t)l * HH,
                                             n_g + (size_t)l * HH,
                                             n_b + (size_t)l * HH,
                                             nullptr, batch, hbuf, aggrbuf, 0);
        }
    }

    segsum_kernel<<<gBlocks, 256>>>(hbuf, vph);
    gemm16<<<gemmG2, 256, GSM_BYTES>>>(nullptr, nullptr, vph, nullptr, 0,
                                       pw1t, nullptr, tr, GG, HH, HH, 0, 1);
    ln_act_kernel<<<GG, 256>>>(tr, p_b1, p_lng, p_lnb, th, HH, 1);
    gemm16<<<gemmG2, 256, GSM_BYTES>>>(nullptr, nullptr, th, nullptr, 0,
                                       pw2t, outbuf, nullptr, GG, HH, HH, 0, 0);
    l2norm_kernel<<<GG, 256>>>(outbuf, p_b2);
}